// round 11
// baseline (speedup 1.0000x reference)
#include <cuda_runtime.h>
#include <cuda_bf16.h>
#include <math.h>
#include <cstdint>

// ---------------- problem constants ----------------
#define NQ   300
#define BSZ  8
#define DIM  256
#define NH   8
#define DH   32
#define DFF  1024
#define STOT 13294
#define NTOK (NQ*BSZ)          // 2400
#define TOKF (NTOK*DIM)        // 614400

// ---------------- scratch (static device globals; no allocations) ----------------
__device__ float g_qbuf [TOKF];
__device__ float g_qh   [TOKF];
__device__ float g_kh   [TOKF];
__device__ float g_vh   [TOKF];
__device__ float g_sain [TOKF];
__device__ float g_saout[TOKF];
__device__ float g_tgt2 [TOKF];
__device__ float g_q2   [TOKF];
__device__ float g_off  [NTOK*768];
__device__ float g_value[(long)BSZ*STOT*DIM];
__device__ float g_cain [TOKF];
__device__ float g_caout[TOKF];
__device__ float g_tgt3 [TOKF];
__device__ float g_f1   [NTOK*DFF];
__device__ float g_f2   [TOKF];

// ---------------- helpers ----------------
__device__ __forceinline__ uint32_t smem_u32(const void* p) {
    uint32_t a;
    asm("{ .reg .u64 t; cvta.to.shared.u64 t, %1; cvt.u32.u64 %0, t; }" : "=r"(a) : "l"(p));
    return a;
}
__device__ __forceinline__ unsigned pk2(__nv_bfloat16 a, __nv_bfloat16 b) {
    __nv_bfloat162 t = __halves2bfloat162(a, b);
    return *reinterpret_cast<unsigned*>(&t);
}
__device__ __forceinline__ void mma_bf16(float* d, const uint32_t* a, uint32_t b0, uint32_t b1) {
    asm volatile(
        "mma.sync.aligned.m16n8k16.row.col.f32.bf16.bf16.f32 "
        "{%0,%1,%2,%3}, {%4,%5,%6,%7}, {%8,%9}, {%0,%1,%2,%3};"
        : "+f"(d[0]), "+f"(d[1]), "+f"(d[2]), "+f"(d[3])
        : "r"(a[0]), "r"(a[1]), "r"(a[2]), "r"(a[3]), "r"(b0), "r"(b1));
}
__device__ __forceinline__ void ldmx4(uint32_t* r, uint32_t addr) {
    asm volatile("ldmatrix.sync.aligned.m8n8.x4.shared.b16 {%0,%1,%2,%3}, [%4];"
                 : "=r"(r[0]), "=r"(r[1]), "=r"(r[2]), "=r"(r[3]) : "r"(addr));
}
__device__ __forceinline__ void cvt_hilo(float4 v, uint2& hi, uint2& lo) {
    __nv_bfloat16 h0 = __float2bfloat16_rn(v.x), h1 = __float2bfloat16_rn(v.y);
    __nv_bfloat16 h2 = __float2bfloat16_rn(v.z), h3 = __float2bfloat16_rn(v.w);
    __nv_bfloat16 l0 = __float2bfloat16_rn(v.x - __bfloat162float(h0));
    __nv_bfloat16 l1 = __float2bfloat16_rn(v.y - __bfloat162float(h1));
    __nv_bfloat16 l2 = __float2bfloat16_rn(v.z - __bfloat162float(h2));
    __nv_bfloat16 l3 = __float2bfloat16_rn(v.w - __bfloat162float(h3));
    hi = make_uint2(pk2(h0, h1), pk2(h2, h3));
    lo = make_uint2(pk2(l0, l1), pk2(l2, l3));
}

// ============ mma.sync bf16 3-term GEMM: C = A(MxK)*W(NxK)^T + bias ============
// fp32 inputs, in-register hi/lo split. CTA 128x128, 256 thr, 8 warps (32x64).
// K chunks of 32, 2-stage smem ping-pong. Stage 32768 B:
//   Ahi 0, Alo 8192, Bhi 16384, Blo 24576. Rows 64B; swz c' = c ^ ((row>>1)&3).
// EPI: 0 plain, 1 relu, 2 head-permute [(b*NH+h)][q][d] (C2 for n>=256),
//      3 pad-mask zero (batched). Nsplit: switch W/bias to W2/bias2 at column Nsplit.
#define STG 32768

template<int EPI>
__global__ void __launch_bounds__(256) mma_gemm(
    const float* __restrict__ A, int lda, long aOff,
    const float* __restrict__ W, int ldw,
    const float* __restrict__ bias,
    const float* __restrict__ W2, const float* __restrict__ bias2, int Nsplit,
    float* __restrict__ C, float* __restrict__ C2, int ldc, long cOff,
    int M, int K,
    const unsigned char* __restrict__ mask, long mOff)
{
    extern __shared__ __align__(128) unsigned char sm[];
    const uint32_t sb = smem_u32(sm);
    const int tid = threadIdx.x;
    const int bm = blockIdx.y * 128;
    const int bn = blockIdx.x * 128;
    A += (long)blockIdx.z * aOff;
    C += (long)blockIdx.z * cOff;
    if (Nsplit && bn >= Nsplit) { W = W2 - (long)Nsplit * ldw; bias = bias2 - Nsplit; }

    const int warp = tid >> 5, lane = tid & 31;
    const int wm = warp & 3, wn = warp >> 2;

    // load geometry: A tile 128x32 = 1024 f4 (4/thr), B same
    int prow[4], pkq[4]; bool agd[4];
    const float* aptr[4]; const float* bptr[4];
    uint32_t psw[4];
#pragma unroll
    for (int j = 0; j < 4; j++) {
        int i = tid + j * 256;
        prow[j] = i >> 3; pkq[j] = i & 7;
        agd[j] = (bm + prow[j]) < M;
        aptr[j] = A + (long)(bm + prow[j]) * lda + pkq[j] * 4;
        bptr[j] = W + (long)(bn + prow[j]) * ldw + pkq[j] * 4;
        psw[j] = (uint32_t)(prow[j] * 64 + (((pkq[j] >> 1) ^ ((prow[j] >> 1) & 3)) << 4) + (pkq[j] & 1) * 8);
    }

    float acc[2][8][4];
#pragma unroll
    for (int mt = 0; mt < 2; mt++)
#pragma unroll
        for (int nt = 0; nt < 8; nt++)
#pragma unroll
            for (int r = 0; r < 4; r++) acc[mt][nt][r] = 0.f;

    const int nk = K >> 5;
    float4 av[4], bv[4];

    // load + stage chunk 0
#pragma unroll
    for (int j = 0; j < 4; j++) {
        av[j] = agd[j] ? *(const float4*)(aptr[j]) : make_float4(0.f,0.f,0.f,0.f);
        bv[j] = *(const float4*)(bptr[j]);
    }
#pragma unroll
    for (int j = 0; j < 4; j++) {
        uint2 hi, lo;
        cvt_hilo(av[j], hi, lo);
        *(uint2*)(sm + psw[j]) = hi;
        *(uint2*)(sm + 8192 + psw[j]) = lo;
        cvt_hilo(bv[j], hi, lo);
        *(uint2*)(sm + 16384 + psw[j]) = hi;
        *(uint2*)(sm + 24576 + psw[j]) = lo;
    }
    __syncthreads();

    for (int kc = 0; kc < nk; kc++) {
        const int st = kc & 1;
        const uint32_t so = sb + (uint32_t)(st * STG);
        const bool more = (kc + 1) < nk;

        // issue gmem loads for next chunk (hidden under MMA)
        if (more) {
            int kb = (kc + 1) * 32;
#pragma unroll
            for (int j = 0; j < 4; j++) {
                av[j] = agd[j] ? *(const float4*)(aptr[j] + kb) : make_float4(0.f,0.f,0.f,0.f);
                bv[j] = *(const float4*)(bptr[j] + kb);
            }
        }

        // compute on current stage: 2 k16 steps, warp tile 32x64
#pragma unroll
        for (int ks = 0; ks < 2; ks++) {
            uint32_t ahi[2][4], alo[2][4];
#pragma unroll
            for (int mt = 0; mt < 2; mt++) {
                int row = wm * 32 + mt * 16 + (lane & 7) + ((lane >> 3) & 1) * 8;
                int c = 2 * ks + (lane >> 4);
                uint32_t off = (uint32_t)(row * 64 + ((c ^ ((row >> 1) & 3)) << 4));
                ldmx4(ahi[mt], so + off);
                ldmx4(alo[mt], so + 8192 + off);
            }
            uint32_t bhi[8][2], blo[8][2];
#pragma unroll
            for (int np = 0; np < 4; np++) {
                int row = wn * 64 + np * 16 + (lane & 7) + (lane >> 4) * 8;
                int c = 2 * ks + ((lane >> 3) & 1);
                uint32_t off = (uint32_t)(row * 64 + ((c ^ ((row >> 1) & 3)) << 4));
                uint32_t t[4];
                ldmx4(t, so + 16384 + off);
                bhi[2*np][0] = t[0]; bhi[2*np][1] = t[1];
                bhi[2*np+1][0] = t[2]; bhi[2*np+1][1] = t[3];
                ldmx4(t, so + 24576 + off);
                blo[2*np][0] = t[0]; blo[2*np][1] = t[1];
                blo[2*np+1][0] = t[2]; blo[2*np+1][1] = t[3];
            }
#pragma unroll
            for (int mt = 0; mt < 2; mt++)
#pragma unroll
                for (int nt = 0; nt < 8; nt++) {
                    mma_bf16(acc[mt][nt], ahi[mt], bhi[nt][0], bhi[nt][1]);
                    mma_bf16(acc[mt][nt], ahi[mt], blo[nt][0], blo[nt][1]);
                    mma_bf16(acc[mt][nt], alo[mt], bhi[nt][0], bhi[nt][1]);
                }
        }

        // convert + store next chunk into other stage
        if (more) {
            const uint32_t po = (uint32_t)((st ^ 1) * STG);
#pragma unroll
            for (int j = 0; j < 4; j++) {
                uint2 hi, lo;
                cvt_hilo(av[j], hi, lo);
                *(uint2*)(sm + po + psw[j]) = hi;
                *(uint2*)(sm + po + 8192 + psw[j]) = lo;
                cvt_hilo(bv[j], hi, lo);
                *(uint2*)(sm + po + 16384 + psw[j]) = hi;
                *(uint2*)(sm + po + 24576 + psw[j]) = lo;
            }
        }
        __syncthreads();
    }

    // ---------------- epilogue ----------------
#pragma unroll
    for (int mt = 0; mt < 2; mt++) {
        int rb = bm + wm * 32 + mt * 16 + (lane >> 2);
#pragma unroll
        for (int nt = 0; nt < 8; nt++) {
            int n0 = bn + wn * 64 + nt * 8 + (lane & 3) * 2;
            float b0 = bias[n0], b1 = bias[n0 + 1];
#pragma unroll
            for (int half = 0; half < 2; half++) {
                int r = rb + half * 8;
                if (r >= M) continue;
                float v0 = acc[mt][nt][half * 2 + 0] + b0;
                float v1 = acc[mt][nt][half * 2 + 1] + b1;
                if (EPI == 1) { v0 = fmaxf(v0, 0.f); v1 = fmaxf(v1, 0.f); }
                if (EPI == 3) {
                    if (mask[(long)blockIdx.z * mOff + r]) { v0 = 0.f; v1 = 0.f; }
                }
                if (EPI == 2) {
                    float* base = C; int nn = n0;
                    if (C2 && nn >= 256) { base = C2; nn -= 256; }
                    int q = r >> 3, bb = r & 7, hh = nn >> 5, d = nn & 31;
                    float* p = base + (((long)(bb * NH + hh)) * NQ + q) * DH + d;
                    p[0] = v0; p[1] = v1;
                } else {
                    float* p = C + (long)r * ldc + n0;
                    p[0] = v0; p[1] = v1;
                }
            }
        }
    }
}

static inline void launch_mma(int epi,
    const float* A, int lda, long aOff,
    const float* W, int ldw, const float* bias,
    const float* W2, const float* bias2, int Nsplit,
    float* C, float* C2, int ldc, long cOff,
    int M, int N, int K, int nz,
    const unsigned char* mask, long mOff)
{
    dim3 grid(N / 128, (M + 127) / 128, nz);
    const int SMEM = 2 * STG;
#define LM(E) do { \
    cudaFuncSetAttribute(mma_gemm<E>, cudaFuncAttributeMaxDynamicSharedMemorySize, SMEM); \
    mma_gemm<E><<<grid,256,SMEM>>>(A,lda,aOff,W,ldw,bias,W2,bias2,Nsplit,C,C2,ldc,cOff,M,K,mask,mOff); } while (0)
    switch (epi) {
        case 0: LM(0); break;
        case 1: LM(1); break;
        case 2: LM(2); break;
        case 3: LM(3); break;
    }
#undef LM
}

// ---------------- elementwise ----------------
__global__ void add_kernel(const float* __restrict__ a, const float* __restrict__ b,
                           float* __restrict__ o, int n4)
{
    int i = blockIdx.x * blockDim.x + threadIdx.x;
    if (i < n4) {
        float4 x = ((const float4*)a)[i], y = ((const float4*)b)[i];
        ((float4*)o)[i] = make_float4(x.x+y.x, x.y+y.y, x.z+y.z, x.w+y.w);
    }
}

__global__ void permadd_kernel(const float* __restrict__ t2, const float* __restrict__ msk,
                               float* __restrict__ q2)
{
    int i = blockIdx.x * 256 + threadIdx.x;   // over TOKF/4 float4s
    if (i >= TOKF/4) return;
    int d4 = i & 63;
    int t = i >> 6;
    int q = t >> 3, b = t & 7;
    float4 x = ((const float4*)t2)[i], y = ((const float4*)msk)[i];
    ((float4*)q2)[((long)(b*NQ + q) << 6) + d4] = make_float4(x.x+y.x, x.y+y.y, x.z+y.z, x.w+y.w);
}

// ---------------- residual + layernorm ----------------
__global__ void __launch_bounds__(256) ln_kernel(
    const float* __restrict__ A, const float* __restrict__ B, int bBQ,
    const float* __restrict__ g, const float* __restrict__ be,
    float* __restrict__ out)
{
    int t = blockIdx.x * 8 + (threadIdx.x >> 5);
    int lane = threadIdx.x & 31;
    if (t >= NTOK) return;
    const float* ap = A + (long)t * DIM + lane*8;
    long bo;
    if (bBQ) { int q = t >> 3, b = t & 7; bo = (long)(b*NQ + q) * DIM; }
    else     { bo = (long)t * DIM; }
    const float* bp = B + bo + lane*8;

    float4 x0 = *(const float4*)ap,      x1 = *(const float4*)(ap + 4);
    float4 y0 = *(const float4*)bp,      y1 = *(const float4*)(bp + 4);
    float v[8] = {x0.x+y0.x, x0.y+y0.y, x0.z+y0.z, x0.w+y0.w,
                  x1.x+y1.x, x1.y+y1.y, x1.z+y1.z, x1.w+y1.w};
    float s = 0.f;
#pragma unroll
    for (int i = 0; i < 8; i++) s += v[i];
#pragma unroll
    for (int o = 16; o; o >>= 1) s += __shfl_xor_sync(0xffffffffu, s, o);
    float mu = s * (1.f/256.f);
    float s2 = 0.f;
#pragma unroll
    for (int i = 0; i < 8; i++) { float d = v[i] - mu; s2 += d*d; }
#pragma unroll
    for (int o = 16; o; o >>= 1) s2 += __shfl_xor_sync(0xffffffffu, s2, o);
    float inv = rsqrtf(s2 * (1.f/256.f) + 1e-5f);
    int c0 = lane*8;
    float* op = out + (long)t * DIM + c0;
#pragma unroll
    for (int i = 0; i < 8; i++)
        op[i] = (v[i] - mu) * inv * g[c0+i] + be[c0+i];
}

// ---------------- fused self-attention ----------------
__global__ void __launch_bounds__(256) attn_kernel(
    const float* __restrict__ qh, const float* __restrict__ kh,
    const float* __restrict__ vh, float* __restrict__ sa_in)
{
    extern __shared__ float smf[];
    const int bh   = blockIdx.x >> 1;
    const int half = blockIdx.x & 1;
    const int b = bh >> 3, h = bh & 7;
    float* Ks = smf;
    float* Vs = Ks + 300*36;
    float* Qs = Vs + 300*36;
    float* Ps = Qs + 150*32;

    const float scale = 0.17677669529663687f;
    const float* Kg = kh + (long)bh * NQ * DH;
    const float* Vg = vh + (long)bh * NQ * DH;
    const float* Qg = qh + (long)bh * NQ * DH + (long)half * 150 * DH;
    const int tid = threadIdx.x;

    for (int i = tid; i < 2400; i += 256) {
        int r = i >> 3, c4 = (i & 7) << 2;
        float4 kv = *(const float4*)(Kg + r*32 + c4);
        float4 vv = *(const float4*)(Vg + r*32 + c4);
        *(float4*)(Ks + r*36 + c4) = kv;
        *(float4*)(Vs + r*36 + c4) = vv;
    }
    for (int i = tid; i < 1200; i += 256) {
        int r = i >> 3, c4 = (i & 7) << 2;
        float4 qv = *(const float4*)(Qg + r*32 + c4);
        qv.x *= scale; qv.y *= scale; qv.z *= scale; qv.w *= scale;
        *(float4*)(Qs + r*32 + c4) = qv;
    }
    __syncthreads();

    const int warp = tid >> 5, lane = tid & 31;
    float* Pw = Ps + warp * 320;

    for (int q = warp; q < 150; q += 8) {
        float4 qr[8];
#pragma unroll
        for (int d4 = 0; d4 < 8; d4++) qr[d4] = *(const float4*)(Qs + q*32 + d4*4);

        float sc[10];
#pragma unroll
        for (int j = 0; j < 10; j++) {
            int k = j*32 + lane;
            float s = -1e30f;
            if (k < 300) {
                s = 0.f;
#pragma unroll
                for (int d4 = 0; d4 < 8; d4++) {
                    float4 kv = *(const float4*)(Ks + k*36 + d4*4);
                    s = fmaf(qr[d4].x, kv.x, s);
                    s = fmaf(qr[d4].y, kv.y, s);
                    s = fmaf(qr[d4].z, kv.z, s);
                    s = fmaf(qr[d4].w, kv.w, s);
                }
            }
            sc[j] = s;
        }
        float m = sc[0];
#pragma unroll
        for (int j = 1; j < 10; j++) m = fmaxf(m, sc[j]);
#pragma unroll
        for (int o = 16; o; o >>= 1) m = fmaxf(m, __shfl_xor_sync(0xffffffffu, m, o));
        float sum = 0.f;
#pragma unroll
        for (int j = 0; j < 10; j++) { sc[j] = expf(sc[j] - m); sum += sc[j]; }
#pragma unroll
        for (int o = 16; o; o >>= 1) sum += __shfl_xor_sync(0xffffffffu, sum, o);
        float inv = 1.f / sum;
#pragma unroll
        for (int j = 0; j < 10; j++) Pw[j*32 + lane] = sc[j] * inv;
        __syncwarp();

        float acc = 0.f;
#pragma unroll 4
        for (int k = 0; k < 300; k++)
            acc = fmaf(Pw[k], Vs[k*36 + lane], acc);

        int qg = half*150 + q;
        sa_in[((long)(qg*BSZ + b)) * DIM + h*DH + lane] = acc;
        __syncwarp();
    }
}

// ---------------- multi-scale deformable sampling ----------------
__global__ void __launch_bounds__(256) deform_kernel(
    const float* __restrict__ offaw,
    const float* __restrict__ bbox, const float* __restrict__ value,
    const int* __restrict__ spatial, const int* __restrict__ lstart,
    float* __restrict__ ca_in)
{
    __shared__ float s_w[8][32][4];
    __shared__ int   s_i[8][32][4];
    int bq = blockIdx.x;
    int b = bq / NQ, q = bq - b*NQ;
    int warp = threadIdx.x >> 5, lane = threadIdx.x & 31;

    const float* tok = offaw + (long)bq * 768;
    float a = tok[512 + warp*32 + lane];
    float m = a;
#pragma unroll
    for (int o = 16; o; o >>= 1) m = fmaxf(m, __shfl_xor_sync(0xffffffffu, m, o));
    float e = expf(a - m);
    float s = e;
#pragma unroll
    for (int o = 16; o; o >>= 1) s += __shfl_xor_sync(0xffffffffu, s, o);
    float p = e / s;

    float ox = tok[warp*64 + lane*2];
    float oy = tok[warp*64 + lane*2 + 1];
    const float* rb = bbox + ((long)q*BSZ + b)*4;
    float r0 = rb[0], r1 = rb[1], r2 = rb[2], r3 = rb[3];

    int lvl = lane >> 3;
    int H = spatial[lvl*2], W = spatial[lvl*2 + 1], ls = lstart[lvl];
    float Wf = (float)W, Hf = (float)H;
    float x = (r0 + ox*0.0625f*r2) * Wf - 0.5f;
    float y = (r1 + oy*0.0625f*r3) * Hf - 0.5f;
    float x0 = floorf(x), y0 = floorf(y);
    float fx = x - x0, fy = y - y0;

#pragma unroll
    for (int c = 0; c < 4; c++) {
        float xi = x0 + (float)(c & 1);
        float yi = y0 + (float)(c >> 1);
        float wgt = ((c & 1) ? fx : 1.f - fx) * ((c >> 1) ? fy : 1.f - fy);
        bool valid = (xi >= 0.f) && (xi < Wf) && (yi >= 0.f) && (yi < Hf);
        int xc = (int)fminf(fmaxf(xi, 0.f), Wf - 1.f);
        int yc = (int)fminf(fmaxf(yi, 0.f), Hf - 1.f);
        s_i[warp][lane][c] = ls + yc*W + xc;
        s_w[warp][lane][c] = valid ? wgt * p : 0.f;
    }
    __syncwarp();

    const float* vb = value + (long)b * STOT * DIM + warp*DH + lane;
    float acc = 0.f;
    for (int lp = 0; lp < 32; lp++) {
#pragma unroll
        for (int c = 0; c < 4; c++) {
            float wgt = s_w[warp][lp][c];
            if (wgt != 0.f)
                acc = fmaf(wgt, vb[(long)s_i[warp][lp][c] << 8], acc);
        }
    }
    ca_in[(long)bq*DIM + warp*DH + lane] = acc;
}

// ---------------- host orchestration (single stream; no allocations) ----------------
extern "C" void kernel_launch(void* const* d_in, const int* in_sizes, int n_in,
                              void* d_out, int out_size)
{
    const float* tgt        = (const float*)d_in[0];
    const float* qmask      = (const float*)d_in[1];
    const float* bbox       = (const float*)d_in[2];
    const float* memory     = (const float*)d_in[4];
    const float* in_proj_w  = (const float*)d_in[5];
    const float* in_proj_b  = (const float*)d_in[6];
    const float* out_sa_w   = (const float*)d_in[7];
    const float* out_sa_b   = (const float*)d_in[8];
    const float* norm2_g    = (const float*)d_in[9];
    const float* norm2_b    = (const float*)d_in[10];
    const float* value_w    = (const float*)d_in[11];
    const float* value_b    = (const float*)d_in[12];
    const float* off_w      = (const float*)d_in[13];
    const float* off_b      = (const float*)d_in[14];
    const float* aw_w       = (const float*)d_in[15];
    const float* aw_b       = (const float*)d_in[16];
    const float* out_ca_w   = (const float*)d_in[17];
    const float* out_ca_b   = (const float*)d_in[18];
    const float* norm1_g    = (const float*)d_in[19];
    const float* norm1_b    = (const float*)d_in[20];
    const float* lin1_w     = (const float*)d_in[21];
    const float* lin1_b     = (const float*)d_in[22];
    const float* lin2_w     = (const float*)d_in[23];
    const float* lin2_b     = (const float*)d_in[24];
    const float* norm3_g    = (const float*)d_in[25];
    const float* norm3_b    = (const float*)d_in[26];
    const unsigned char* pmask = (const unsigned char*)d_in[27];
    const int* spatial      = (const int*)d_in[28];
    const int* lstart       = (const int*)d_in[29];
    float* out = (float*)d_out;

    float *qbuf,*qh,*kh,*vh,*sain,*saout,*tgt2,*q2,*offb,*val,*cain,*caout,*tgt3,*f1,*f2;
    cudaGetSymbolAddress((void**)&qbuf,  g_qbuf);
    cudaGetSymbolAddress((void**)&qh,    g_qh);
    cudaGetSymbolAddress((void**)&kh,    g_kh);
    cudaGetSymbolAddress((void**)&vh,    g_vh);
    cudaGetSymbolAddress((void**)&sain,  g_sain);
    cudaGetSymbolAddress((void**)&saout, g_saout);
    cudaGetSymbolAddress((void**)&tgt2,  g_tgt2);
    cudaGetSymbolAddress((void**)&q2,    g_q2);
    cudaGetSymbolAddress((void**)&offb,  g_off);
    cudaGetSymbolAddress((void**)&val,   g_value);
    cudaGetSymbolAddress((void**)&cain,  g_cain);
    cudaGetSymbolAddress((void**)&caout, g_caout);
    cudaGetSymbolAddress((void**)&tgt3,  g_tgt3);
    cudaGetSymbolAddress((void**)&f1,    g_f1);
    cudaGetSymbolAddress((void**)&f2,    g_f2);

    // 1) q = tgt + query_mask
    add_kernel<<<TOKF/4/256, 256>>>(tgt, qmask, qbuf, TOKF/4);

    // 2) value projection over memory (batched over BS), pad-mask epilogue
    launch_mma(3, memory, BSZ*DIM, 256, value_w, DIM, value_b,
               nullptr, nullptr, 0,
               val, nullptr, DIM, (long)STOT*DIM,
               STOT, DIM, DIM, BSZ, pmask, STOT);

    // 3) Q+K merged (N=512), then V
    launch_mma(2, qbuf, DIM, 0, in_proj_w, DIM, in_proj_b,
               nullptr, nullptr, 0, qh, kh, 0, 0, NTOK, 512, DIM, 1, nullptr, 0);
    launch_mma(2, tgt, DIM, 0, in_proj_w + 512*256, DIM, in_proj_b + 512,
               nullptr, nullptr, 0, vh, nullptr, 0, 0, NTOK, 256, DIM, 1, nullptr, 0);

    // 4) fused self-attention
    {
        int smem = (300*36*2 + 150*32 + 8*320) * 4;
        cudaFuncSetAttribute(attn_kernel, cudaFuncAttributeMaxDynamicSharedMemorySize, smem);
        attn_kernel<<<128, 256, smem>>>(qh, kh, vh, sain);
    }

    // 5) self-attn out-proj + residual LN (norm2)
    launch_mma(0, sain, DIM, 0, out_sa_w, DIM, out_sa_b,
               nullptr, nullptr, 0, saout, nullptr, DIM, 0, NTOK, DIM, DIM, 1, nullptr, 0);
    ln_kernel<<<NTOK/8, 256>>>(tgt, saout, 0, norm2_g, norm2_b, tgt2);

    // 6) query2 = (tgt2 + mask) in (b,q,d) layout
    permadd_kernel<<<(TOKF/4 + 255)/256, 256>>>(tgt2, qmask, q2);

    // 7) offsets + aw logits merged (N=768, split at 512)
    launch_mma(0, q2, DIM, 0, off_w, DIM, off_b,
               aw_w, aw_b, 512,
               offb, nullptr, 768, 0, NTOK, 768, DIM, 1, nullptr, 0);

    // 8) deformable sampling
    deform_kernel<<<NTOK, 256>>>(offb, bbox, val, spatial, lstart, cain);

    // 9) cross-attn out-proj + residual LN (norm1)
    launch_mma(0, cain, DIM, 0, out_ca_w, DIM, out_ca_b,
               nullptr, nullptr, 0, caout, nullptr, DIM, 0, NTOK, DIM, DIM, 1, nullptr, 0);
    ln_kernel<<<NTOK/8, 256>>>(tgt2, caout, 1, norm1_g, norm1_b, tgt3);

    // 10) FFN + final LN (norm3) -> d_out
    launch_mma(1, tgt3, DIM, 0, lin1_w, DIM, lin1_b,
               nullptr, nullptr, 0, f1, nullptr, DFF, 0, NTOK, DFF, DIM, 1, nullptr, 0);
    launch_mma(0, f1, DFF, 0, lin2_w, DFF, lin2_b,
               nullptr, nullptr, 0, f2, nullptr, DIM, 0, NTOK, DIM, DFF, 1, nullptr, 0);
    ln_kernel<<<NTOK/8, 256>>>(tgt3, f2, 0, norm3_g, norm3_b, out);
}

// round 12
// speedup vs baseline: 1.0926x; 1.0926x over previous
#include <cuda_runtime.h>
#include <cuda_bf16.h>
#include <math.h>
#include <cstdint>

// ---------------- problem constants ----------------
#define NQ   300
#define BSZ  8
#define DIM  256
#define NH   8
#define DH   32
#define DFF  1024
#define STOT 13294
#define NTOK (NQ*BSZ)          // 2400
#define TOKF (NTOK*DIM)        // 614400

// weight plane offsets (elements)
#define W_INPROJ 0L
#define W_OUTSA  196608L
#define W_VALUE  262144L
#define W_OFF    327680L
#define W_AW     458752L
#define W_OUTCA  524288L
#define W_LIN1   589824L
#define W_LIN2   851968L
#define W_TOTAL  1114112L

// ---------------- scratch (static device globals; no allocations) ----------------
__device__ float g_qh   [TOKF];
__device__ float g_kh   [TOKF];
__device__ float g_vh   [TOKF];
__device__ float g_saout[TOKF];
__device__ float g_tgt2 [TOKF];
__device__ float g_off  [NTOK*768];
__device__ float g_value[(long)BSZ*STOT*DIM];
__device__ float g_caout[TOKF];
__device__ float g_tgt3 [TOKF];
__device__ float g_f2   [TOKF];

// bf16 hi/lo planes (small tensors + weights only; NO memory planes)
__device__ __nv_bfloat16 g_wh[W_TOTAL], g_wl[W_TOTAL];
__device__ __nv_bfloat16 g_qbh[TOKF], g_qbl[TOKF];     // tgt+mask (QK input)
__device__ __nv_bfloat16 g_tgh[TOKF], g_tgl[TOKF];     // tgt (V input)
__device__ __nv_bfloat16 g_sah[TOKF], g_sal[TOKF];     // attn out
__device__ __nv_bfloat16 g_q2h[TOKF], g_q2l[TOKF];     // query2
__device__ __nv_bfloat16 g_t3h[TOKF], g_t3l[TOKF];     // tgt3
__device__ __nv_bfloat16 g_f1h[NTOK*DFF], g_f1l[NTOK*DFF];
__device__ __nv_bfloat16 g_cah[TOKF], g_cal[TOKF];     // deform out

// ---------------- helpers ----------------
__device__ __forceinline__ uint32_t smem_u32(const void* p) {
    uint32_t a;
    asm("{ .reg .u64 t; cvta.to.shared.u64 t, %1; cvt.u32.u64 %0, t; }" : "=r"(a) : "l"(p));
    return a;
}
__device__ __forceinline__ unsigned pk2(__nv_bfloat16 a, __nv_bfloat16 b) {
    __nv_bfloat162 t = __halves2bfloat162(a, b);
    return *reinterpret_cast<unsigned*>(&t);
}
__device__ __forceinline__ void mma_bf16(float* d, const uint32_t* a, uint32_t b0, uint32_t b1) {
    asm volatile(
        "mma.sync.aligned.m16n8k16.row.col.f32.bf16.bf16.f32 "
        "{%0,%1,%2,%3}, {%4,%5,%6,%7}, {%8,%9}, {%0,%1,%2,%3};"
        : "+f"(d[0]), "+f"(d[1]), "+f"(d[2]), "+f"(d[3])
        : "r"(a[0]), "r"(a[1]), "r"(a[2]), "r"(a[3]), "r"(b0), "r"(b1));
}
__device__ __forceinline__ void ldmx4(uint32_t* r, uint32_t addr) {
    asm volatile("ldmatrix.sync.aligned.m8n8.x4.shared.b16 {%0,%1,%2,%3}, [%4];"
                 : "=r"(r[0]), "=r"(r[1]), "=r"(r[2]), "=r"(r[3]) : "r"(addr));
}
#define CP16(dst, src, sz) \
    asm volatile("cp.async.cg.shared.global [%0], [%1], 16, %2;" \
                 :: "r"(dst), "l"(src), "r"(sz) : "memory")
#define CP_COMMIT() asm volatile("cp.async.commit_group;" ::: "memory")
#define CP_WAIT1()  asm volatile("cp.async.wait_group 1;" ::: "memory")

__device__ __forceinline__ void split8(const float* v, unsigned* hi, unsigned* lo) {
    __nv_bfloat16 h[4], l[4];
#pragma unroll
    for (int i = 0; i < 4; i++) {
        h[i] = __float2bfloat16_rn(v[i]);
        l[i] = __float2bfloat16_rn(v[i] - __bfloat162float(h[i]));
    }
    hi[0] = pk2(h[0], h[1]); hi[1] = pk2(h[2], h[3]);
    lo[0] = pk2(l[0], l[1]); lo[1] = pk2(l[2], l[3]);
}
__device__ __forceinline__ void cvt_hilo(float4 v, uint2& hi, uint2& lo) {
    unsigned h[2], l[2];
    split8(&v.x, h, l);
    hi = make_uint2(h[0], h[1]);
    lo = make_uint2(l[0], l[1]);
}

// ============ plane-plane bf16 3-term GEMM (R5-proven): C = A*W^T + bias ============
// Both operands pre-split planes. CTA 128x128, 256 thr, 8 warps (32x64).
// cp.async 3-stage, K chunks of 32. Stage 32768 B: Ahi 0, Alo 8192, Bhi 16384, Blo 24576.
// EPI: 0 plain fp32, 1 relu -> planes, 2 head-permute fp32 (C/C2 split at 256).
template<int EPI>
__global__ void __launch_bounds__(256, 2) mma_pp(
    const __nv_bfloat16* __restrict__ Ahi, const __nv_bfloat16* __restrict__ Alo,
    int lda,
    const __nv_bfloat16* __restrict__ Bhi, const __nv_bfloat16* __restrict__ Blo,
    int ldw, const float* __restrict__ bias,
    const __nv_bfloat16* W2hi, const __nv_bfloat16* W2lo,
    const float* bias2, int Nsplit,
    float* __restrict__ C, float* __restrict__ C2,
    __nv_bfloat16* __restrict__ Chi, __nv_bfloat16* __restrict__ Clo,
    int ldc, int M, int K)
{
    extern __shared__ __align__(128) unsigned char sm[];
    const uint32_t sb = smem_u32(sm);
    const int tid = threadIdx.x;
    const int bm = blockIdx.y * 128;
    const int bn = blockIdx.x * 128;
    if (Nsplit && bn >= Nsplit) {
        Bhi = W2hi - (long)Nsplit * ldw;
        Blo = W2lo - (long)Nsplit * ldw;
        bias = bias2 - Nsplit;
    }

    const int warp = tid >> 5, lane = tid & 31;
    const int wm = warp & 3, wn = warp >> 2;

    const int r0 = tid >> 2, r1 = r0 + 64;
    const int ch = tid & 3;
    const uint32_t d0 = (uint32_t)(r0 * 64 + ((ch ^ ((r0 >> 1) & 3)) << 4));
    const uint32_t d1 = (uint32_t)(r1 * 64 + ((ch ^ ((r1 >> 1) & 3)) << 4));
    const int am0 = bm + r0 < M ? bm + r0 : M - 1;
    const int am1 = bm + r1 < M ? bm + r1 : M - 1;
    const uint32_t sz0 = (bm + r0 < M) ? 16u : 0u;
    const uint32_t sz1 = (bm + r1 < M) ? 16u : 0u;
    const long aro0 = (long)am0 * lda + ch * 8;
    const long aro1 = (long)am1 * lda + ch * 8;
    const long bro0 = (long)(bn + r0) * ldw + ch * 8;
    const long bro1 = (long)(bn + r1) * ldw + ch * 8;

    const int nk = K >> 5;

#define ISSUE(kc, st) do { \
    if ((kc) < nk) { \
        const int kb = (kc) * 32; \
        const uint32_t so = sb + (uint32_t)((st) * 32768); \
        CP16(so + d0,          Ahi + aro0 + kb, sz0); \
        CP16(so + d1,          Ahi + aro1 + kb, sz1); \
        CP16(so + 8192  + d0,  Alo + aro0 + kb, sz0); \
        CP16(so + 8192  + d1,  Alo + aro1 + kb, sz1); \
        CP16(so + 16384 + d0,  Bhi + bro0 + kb, 16u); \
        CP16(so + 16384 + d1,  Bhi + bro1 + kb, 16u); \
        CP16(so + 24576 + d0,  Blo + bro0 + kb, 16u); \
        CP16(so + 24576 + d1,  Blo + bro1 + kb, 16u); \
    } \
    CP_COMMIT(); \
} while (0)

    float acc[2][8][4];
#pragma unroll
    for (int mt = 0; mt < 2; mt++)
#pragma unroll
        for (int nt = 0; nt < 8; nt++)
#pragma unroll
            for (int r = 0; r < 4; r++) acc[mt][nt][r] = 0.f;

    ISSUE(0, 0);
    ISSUE(1, 1);

    for (int kc = 0; kc < nk; kc++) {
        CP_WAIT1();
        __syncthreads();
        ISSUE(kc + 2, (kc + 2) % 3);

        const uint32_t so = sb + (uint32_t)((kc % 3) * 32768);
#pragma unroll
        for (int ks = 0; ks < 2; ks++) {
            uint32_t ahi[2][4], alo[2][4];
#pragma unroll
            for (int mt = 0; mt < 2; mt++) {
                int row = wm * 32 + mt * 16 + (lane & 7) + ((lane >> 3) & 1) * 8;
                int c = 2 * ks + (lane >> 4);
                uint32_t off = (uint32_t)(row * 64 + ((c ^ ((row >> 1) & 3)) << 4));
                ldmx4(ahi[mt], so + off);
                ldmx4(alo[mt], so + 8192 + off);
            }
            uint32_t bhi[8][2], blo[8][2];
#pragma unroll
            for (int np = 0; np < 4; np++) {
                int row = wn * 64 + np * 16 + (lane & 7) + (lane >> 4) * 8;
                int c = 2 * ks + ((lane >> 3) & 1);
                uint32_t off = (uint32_t)(row * 64 + ((c ^ ((row >> 1) & 3)) << 4));
                uint32_t t[4];
                ldmx4(t, so + 16384 + off);
                bhi[2*np][0] = t[0]; bhi[2*np][1] = t[1];
                bhi[2*np+1][0] = t[2]; bhi[2*np+1][1] = t[3];
                ldmx4(t, so + 24576 + off);
                blo[2*np][0] = t[0]; blo[2*np][1] = t[1];
                blo[2*np+1][0] = t[2]; blo[2*np+1][1] = t[3];
            }
#pragma unroll
            for (int mt = 0; mt < 2; mt++)
#pragma unroll
                for (int nt = 0; nt < 8; nt++) {
                    mma_bf16(acc[mt][nt], ahi[mt], bhi[nt][0], bhi[nt][1]);
                    mma_bf16(acc[mt][nt], ahi[mt], blo[nt][0], blo[nt][1]);
                    mma_bf16(acc[mt][nt], alo[mt], bhi[nt][0], bhi[nt][1]);
                }
        }
    }
#undef ISSUE

    // epilogue
#pragma unroll
    for (int mt = 0; mt < 2; mt++) {
        int rb = bm + wm * 32 + mt * 16 + (lane >> 2);
#pragma unroll
        for (int nt = 0; nt < 8; nt++) {
            int n0 = bn + wn * 64 + nt * 8 + (lane & 3) * 2;
            float b0 = bias[n0], b1 = bias[n0 + 1];
#pragma unroll
            for (int half = 0; half < 2; half++) {
                int r = rb + half * 8;
                if (r >= M) continue;
                float v0 = acc[mt][nt][half * 2 + 0] + b0;
                float v1 = acc[mt][nt][half * 2 + 1] + b1;
                if (EPI == 1) {
                    v0 = fmaxf(v0, 0.f); v1 = fmaxf(v1, 0.f);
                    __nv_bfloat16 h0 = __float2bfloat16_rn(v0);
                    __nv_bfloat16 h1 = __float2bfloat16_rn(v1);
                    long p = (long)r * ldc + n0;
                    *(__nv_bfloat162*)(Chi + p) = __halves2bfloat162(h0, h1);
                    *(__nv_bfloat162*)(Clo + p) = __halves2bfloat162(
                        __float2bfloat16_rn(v0 - __bfloat162float(h0)),
                        __float2bfloat16_rn(v1 - __bfloat162float(h1)));
                } else if (EPI == 2) {
                    float* base = C; int nn = n0;
                    if (nn >= 256) { base = C2; nn -= 256; }
                    int q = r >> 3, bb = r & 7, hh = nn >> 5, d = nn & 31;
                    float* p = base + (((long)(bb * NH + hh)) * NQ + q) * DH + d;
                    p[0] = v0; p[1] = v1;
                } else {
                    float* p = C + (long)r * ldc + n0;
                    p[0] = v0; p[1] = v1;
                }
            }
        }
    }
}

static inline void launch_pp(int epi,
    const __nv_bfloat16* Ahi, const __nv_bfloat16* Alo, int lda,
    const __nv_bfloat16* Bhi, const __nv_bfloat16* Blo, int ldw, const float* bias,
    const __nv_bfloat16* W2hi, const __nv_bfloat16* W2lo, const float* bias2, int Nsplit,
    float* C, float* C2, __nv_bfloat16* Chi, __nv_bfloat16* Clo, int ldc,
    int M, int N, int K)
{
    dim3 grid(N / 128, (M + 127) / 128);
    const int SMEM = 3 * 32768;
#define LM(E) do { \
    cudaFuncSetAttribute(mma_pp<E>, cudaFuncAttributeMaxDynamicSharedMemorySize, SMEM); \
    mma_pp<E><<<grid,256,SMEM>>>(Ahi,Alo,lda,Bhi,Blo,ldw,bias,W2hi,W2lo,bias2,Nsplit, \
                                 C,C2,Chi,Clo,ldc,M,K); } while (0)
    switch (epi) { case 0: LM(0); break; case 1: LM(1); break; case 2: LM(2); break; }
#undef LM
}

// ============ value GEMM: fp32 A (memory, batched) x plane W; R7 structure ============
// CTA 64x128, 256 thr, 8 warps (32x32). K chunks 32, 2-stage ping-pong.
// Stage 24576 B: Ahi 0, Alo 4096, Bhi 8192, Blo 16384.
#define VSTG 24576
__global__ void __launch_bounds__(256, 2) mma_val(
    const float* __restrict__ A, int lda, long aOff,
    const __nv_bfloat16* __restrict__ Bhi, const __nv_bfloat16* __restrict__ Blo,
    int ldw, const float* __restrict__ bias,
    float* __restrict__ C, long cOff, int ldc,
    int M, int K,
    const unsigned char* __restrict__ mask, long mOff)
{
    extern __shared__ __align__(128) unsigned char sm[];
    const uint32_t sb = smem_u32(sm);
    const int tid = threadIdx.x;
    const int bm = blockIdx.y * 64;
    const int bn = blockIdx.x * 128;
    A += (long)blockIdx.z * aOff;
    C += (long)blockIdx.z * cOff;

    const int warp = tid >> 5, lane = tid & 31;
    const int wm = warp & 1, wn = warp >> 1;

    // A: 64 rows x 32 k fp32 = 512 f4 (2/thr)
    int arow[2], akq[2]; bool agd[2]; const float* aptr[2]; uint32_t asw[2];
#pragma unroll
    for (int j = 0; j < 2; j++) {
        int i = tid + j * 256;
        arow[j] = i >> 3; akq[j] = i & 7;
        agd[j] = (bm + arow[j]) < M;
        aptr[j] = A + (long)(bm + arow[j]) * lda + akq[j] * 4;
        asw[j] = (uint32_t)(arow[j] * 64 + (((akq[j] >> 1) ^ ((arow[j] >> 1) & 3)) << 4) + (akq[j] & 1) * 8);
    }
    // B planes: 128 rows x 32 k bf16 = 8KB/plane; 2x16B per thread per plane
    const int br0 = tid >> 2, br1 = br0 + 64;
    const int bch = tid & 3;
    const uint32_t bd0 = (uint32_t)(br0 * 64 + ((bch ^ ((br0 >> 1) & 3)) << 4));
    const uint32_t bd1 = (uint32_t)(br1 * 64 + ((bch ^ ((br1 >> 1) & 3)) << 4));
    const long bro0 = (long)(bn + br0) * ldw + bch * 8;
    const long bro1 = (long)(bn + br1) * ldw + bch * 8;

    float acc[2][4][4];
#pragma unroll
    for (int mt = 0; mt < 2; mt++)
#pragma unroll
        for (int nt = 0; nt < 4; nt++)
#pragma unroll
            for (int r = 0; r < 4; r++) acc[mt][nt][r] = 0.f;

    const int nk = K >> 5;
    float4 av[2];
    uint4 bh0, bh1, bl0, bl1;

    // stage chunk 0
#pragma unroll
    for (int j = 0; j < 2; j++)
        av[j] = agd[j] ? *(const float4*)(aptr[j]) : make_float4(0.f,0.f,0.f,0.f);
    bh0 = *(const uint4*)(Bhi + bro0); bh1 = *(const uint4*)(Bhi + bro1);
    bl0 = *(const uint4*)(Blo + bro0); bl1 = *(const uint4*)(Blo + bro1);
#pragma unroll
    for (int j = 0; j < 2; j++) {
        uint2 hi, lo; cvt_hilo(av[j], hi, lo);
        *(uint2*)(sm + asw[j]) = hi;
        *(uint2*)(sm + 4096 + asw[j]) = lo;
    }
    *(uint4*)(sm + 8192 + bd0) = bh0;  *(uint4*)(sm + 8192 + bd1) = bh1;
    *(uint4*)(sm + 16384 + bd0) = bl0; *(uint4*)(sm + 16384 + bd1) = bl1;
    __syncthreads();

    for (int kc = 0; kc < nk; kc++) {
        const int st = kc & 1;
        const uint32_t so = sb + (uint32_t)(st * VSTG);
        const bool more = (kc + 1) < nk;

        if (more) {
            int kb = (kc + 1) * 32;
#pragma unroll
            for (int j = 0; j < 2; j++)
                av[j] = agd[j] ? *(const float4*)(aptr[j] + kb) : make_float4(0.f,0.f,0.f,0.f);
            bh0 = *(const uint4*)(Bhi + bro0 + kb); bh1 = *(const uint4*)(Bhi + bro1 + kb);
            bl0 = *(const uint4*)(Blo + bro0 + kb); bl1 = *(const uint4*)(Blo + bro1 + kb);
        }

#pragma unroll
        for (int ks = 0; ks < 2; ks++) {
            uint32_t ahi[2][4], alo[2][4];
#pragma unroll
            for (int mt = 0; mt < 2; mt++) {
                int row = wm * 32 + mt * 16 + (lane & 7) + ((lane >> 3) & 1) * 8;
                int c = 2 * ks + (lane >> 4);
                uint32_t off = (uint32_t)(row * 64 + ((c ^ ((row >> 1) & 3)) << 4));
                ldmx4(ahi[mt], so + off);
                ldmx4(alo[mt], so + 4096 + off);
            }
            uint32_t bhi[4][2], blo[4][2];
#pragma unroll
            for (int np = 0; np < 2; np++) {
                int row = wn * 32 + np * 16 + (lane & 7) + (lane >> 4) * 8;
                int c = 2 * ks + ((lane >> 3) & 1);
                uint32_t off = (uint32_t)(row * 64 + ((c ^ ((row >> 1) & 3)) << 4));
                uint32_t t[4];
                ldmx4(t, so + 8192 + off);
                bhi[2*np][0] = t[0]; bhi[2*np][1] = t[1];
                bhi[2*np+1][0] = t[2]; bhi[2*np+1][1] = t[3];
                ldmx4(t, so + 16384 + off);
                blo[2*np][0] = t[0]; blo[2*np][1] = t[1];
                blo[2*np+1][0] = t[2]; blo[2*np+1][1] = t[3];
            }
#pragma unroll
            for (int mt = 0; mt < 2; mt++)
#pragma unroll
                for (int nt = 0; nt < 4; nt++) {
                    mma_bf16(acc[mt][nt], ahi[mt], bhi[nt][0], bhi[nt][1]);
                    mma_bf16(acc[mt][nt], ahi[mt], blo[nt][0], blo[nt][1]);
                    mma_bf16(acc[mt][nt], alo[mt], bhi[nt][0], bhi[nt][1]);
                }
        }

        if (more) {
            const uint32_t po = (uint32_t)((st ^ 1) * VSTG);
#pragma unroll
            for (int j = 0; j < 2; j++) {
                uint2 hi, lo; cvt_hilo(av[j], hi, lo);
                *(uint2*)(sm + po + asw[j]) = hi;
                *(uint2*)(sm + po + 4096 + asw[j]) = lo;
            }
            *(uint4*)(sm + po + 8192 + bd0) = bh0;  *(uint4*)(sm + po + 8192 + bd1) = bh1;
            *(uint4*)(sm + po + 16384 + bd0) = bl0; *(uint4*)(sm + po + 16384 + bd1) = bl1;
        }
        __syncthreads();
    }

    // epilogue (pad-mask zero)
#pragma unroll
    for (int mt = 0; mt < 2; mt++) {
        int r0 = bm + wm * 32 + mt * 16 + (lane >> 2);
#pragma unroll
        for (int nt = 0; nt < 4; nt++) {
            int n0 = bn + wn * 32 + nt * 8 + (lane & 3) * 2;
            float b0 = bias[n0], b1 = bias[n0 + 1];
#pragma unroll
            for (int half = 0; half < 2; half++) {
                int r = r0 + half * 8;
                if (r >= M) continue;
                float v0 = acc[mt][nt][half * 2 + 0] + b0;
                float v1 = acc[mt][nt][half * 2 + 1] + b1;
                if (mask[(long)blockIdx.z * mOff + r]) { v0 = 0.f; v1 = 0.f; }
                float* p = C + (long)r * ldc + n0;
                p[0] = v0; p[1] = v1;
            }
        }
    }
}

// ---------------- converts ----------------
struct WDesc { const float* src[8]; long off[8]; int n4[8]; };
__global__ void cvt_w_kernel(WDesc d, __nv_bfloat16* __restrict__ hi, __nv_bfloat16* __restrict__ lo)
{
    int w = blockIdx.y;
    int i = blockIdx.x * blockDim.x + threadIdx.x;
    if (i >= d.n4[w]) return;
    float4 v = ((const float4*)d.src[w])[i];
    unsigned h[2], l[2];
    split8(&v.x, h, l);
    ((uint2*)(hi + d.off[w]))[i] = make_uint2(h[0], h[1]);
    ((uint2*)(lo + d.off[w]))[i] = make_uint2(l[0], l[1]);
}

// fused: qb = tgt+mask planes, tg = tgt planes
__global__ void add_cvt2_kernel(const float* __restrict__ a, const float* __restrict__ b,
                                __nv_bfloat16* __restrict__ qhi, __nv_bfloat16* __restrict__ qlo,
                                __nv_bfloat16* __restrict__ thi, __nv_bfloat16* __restrict__ tlo)
{
    int i = blockIdx.x * 256 + threadIdx.x;
    if (i >= TOKF/4) return;
    float4 x = ((const float4*)a)[i], y = ((const float4*)b)[i];
    unsigned h[2], l[2];
    split8(&x.x, h, l);
    ((uint2*)thi)[i] = make_uint2(h[0], h[1]);
    ((uint2*)tlo)[i] = make_uint2(l[0], l[1]);
    float v[4] = {x.x+y.x, x.y+y.y, x.z+y.z, x.w+y.w};
    split8(v, h, l);
    ((uint2*)qhi)[i] = make_uint2(h[0], h[1]);
    ((uint2*)qlo)[i] = make_uint2(l[0], l[1]);
}

// query2 planes in (b,q,d) layout
__global__ void permadd_cvt_kernel(const float* __restrict__ t2, const float* __restrict__ msk,
                                   __nv_bfloat16* __restrict__ hi, __nv_bfloat16* __restrict__ lo)
{
    int i = blockIdx.x * 256 + threadIdx.x;
    if (i >= TOKF/4) return;
    int d4 = i & 63;
    int t = i >> 6;
    int q = t >> 3, b = t & 7;
    float4 x = ((const float4*)t2)[i], y = ((const float4*)msk)[i];
    float v[4] = {x.x+y.x, x.y+y.y, x.z+y.z, x.w+y.w};
    unsigned h[2], l[2];
    split8(v, h, l);
    long o = ((long)(b*NQ + q) << 6) + d4;
    ((uint2*)hi)[o] = make_uint2(h[0], h[1]);
    ((uint2*)lo)[o] = make_uint2(l[0], l[1]);
}

// ---------------- residual + layernorm (optional plane out) ----------------
__global__ void __launch_bounds__(256) ln_kernel(
    const float* __restrict__ A, const float* __restrict__ B, int bBQ,
    const float* __restrict__ g, const float* __restrict__ be,
    float* __restrict__ out,
    __nv_bfloat16* __restrict__ ohi, __nv_bfloat16* __restrict__ olo)
{
    int t = blockIdx.x * 8 + (threadIdx.x >> 5);
    int lane = threadIdx.x & 31;
    if (t >= NTOK) return;
    const float* ap = A + (long)t * DIM + lane*8;
    long bo;
    if (bBQ) { int q = t >> 3, b = t & 7; bo = (long)(b*NQ + q) * DIM; }
    else     { bo = (long)t * DIM; }
    const float* bp = B + bo + lane*8;

    float4 x0 = *(const float4*)ap,      x1 = *(const float4*)(ap + 4);
    float4 y0 = *(const float4*)bp,      y1 = *(const float4*)(bp + 4);
    float v[8] = {x0.x+y0.x, x0.y+y0.y, x0.z+y0.z, x0.w+y0.w,
                  x1.x+y1.x, x1.y+y1.y, x1.z+y1.z, x1.w+y1.w};
    float s = 0.f;
#pragma unroll
    for (int i = 0; i < 8; i++) s += v[i];
#pragma unroll
    for (int o = 16; o; o >>= 1) s += __shfl_xor_sync(0xffffffffu, s, o);
    float mu = s * (1.f/256.f);
    float s2 = 0.f;
#pragma unroll
    for (int i = 0; i < 8; i++) { float d = v[i] - mu; s2 += d*d; }
#pragma unroll
    for (int o = 16; o; o >>= 1) s2 += __shfl_xor_sync(0xffffffffu, s2, o);
    float inv = rsqrtf(s2 * (1.f/256.f) + 1e-5f);
    int c0 = lane*8;
    float* op = out + (long)t * DIM + c0;
    float r[8];
#pragma unroll
    for (int i = 0; i < 8; i++) {
        r[i] = (v[i] - mu) * inv * g[c0+i] + be[c0+i];
        op[i] = r[i];
    }
    if (ohi) {
        unsigned h[2], l[2], h2[2], l2[2];
        split8(r, h, l);
        split8(r + 4, h2, l2);
        long o4 = ((long)t * DIM + c0) >> 2;
        ((uint2*)ohi)[o4]   = make_uint2(h[0], h[1]);
        ((uint2*)ohi)[o4+1] = make_uint2(h2[0], h2[1]);
        ((uint2*)olo)[o4]   = make_uint2(l[0], l[1]);
        ((uint2*)olo)[o4+1] = make_uint2(l2[0], l2[1]);
    }
}

// ---------------- fused self-attention (writes planes) ----------------
__global__ void __launch_bounds__(256) attn_kernel(
    const float* __restrict__ qh, const float* __restrict__ kh,
    const float* __restrict__ vh,
    __nv_bfloat16* __restrict__ sah, __nv_bfloat16* __restrict__ sal)
{
    extern __shared__ float smf[];
    const int bh   = blockIdx.x >> 1;
    const int half = blockIdx.x & 1;
    const int b = bh >> 3, h = bh & 7;
    float* Ks = smf;
    float* Vs = Ks + 300*36;
    float* Qs = Vs + 300*36;
    float* Ps = Qs + 150*32;

    const float scale = 0.17677669529663687f;
    const float* Kg = kh + (long)bh * NQ * DH;
    const float* Vg = vh + (long)bh * NQ * DH;
    const float* Qg = qh + (long)bh * NQ * DH + (long)half * 150 * DH;
    const int tid = threadIdx.x;

    for (int i = tid; i < 2400; i += 256) {
        int r = i >> 3, c4 = (i & 7) << 2;
        float4 kv = *(const float4*)(Kg + r*32 + c4);
        float4 vv = *(const float4*)(Vg + r*32 + c4);
        *(float4*)(Ks + r*36 + c4) = kv;
        *(float4*)(Vs + r*36 + c4) = vv;
    }
    for (int i = tid; i < 1200; i += 256) {
        int r = i >> 3, c4 = (i & 7) << 2;
        float4 qv = *(const float4*)(Qg + r*32 + c4);
        qv.x *= scale; qv.y *= scale; qv.z *= scale; qv.w *= scale;
        *(float4*)(Qs + r*32 + c4) = qv;
    }
    __syncthreads();

    const int warp = tid >> 5, lane = tid & 31;
    float* Pw = Ps + warp * 320;

    for (int q = warp; q < 150; q += 8) {
        float4 qr[8];
#pragma unroll
        for (int d4 = 0; d4 < 8; d4++) qr[d4] = *(const float4*)(Qs + q*32 + d4*4);

        float sc[10];
#pragma unroll
        for (int j = 0; j < 10; j++) {
            int k = j*32 + lane;
            float s = -1e30f;
            if (k < 300) {
                s = 0.f;
#pragma unroll
                for (int d4 = 0; d4 < 8; d4++) {
                    float4 kv = *(const float4*)(Ks + k*36 + d4*4);
                    s = fmaf(qr[d4].x, kv.x, s);
                    s = fmaf(qr[d4].y, kv.y, s);
                    s = fmaf(qr[d4].z, kv.z, s);
                    s = fmaf(qr[d4].w, kv.w, s);
                }
            }
            sc[j] = s;
        }
        float m = sc[0];
#pragma unroll
        for (int j = 1; j < 10; j++) m = fmaxf(m, sc[j]);
#pragma unroll
        for (int o = 16; o; o >>= 1) m = fmaxf(m, __shfl_xor_sync(0xffffffffu, m, o));
        float sum = 0.f;
#pragma unroll
        for (int j = 0; j < 10; j++) { sc[j] = expf(sc[j] - m); sum += sc[j]; }
#pragma unroll
        for (int o = 16; o; o >>= 1) sum += __shfl_xor_sync(0xffffffffu, sum, o);
        float inv = 1.f / sum;
#pragma unroll
        for (int j = 0; j < 10; j++) Pw[j*32 + lane] = sc[j] * inv;
        __syncwarp();

        float acc = 0.f;
#pragma unroll 4
        for (int k = 0; k < 300; k++)
            acc = fmaf(Pw[k], Vs[k*36 + lane], acc);

        int qg = half*150 + q;
        long o = ((long)(qg*BSZ + b)) * DIM + h*DH + lane;
        __nv_bfloat16 hi = __float2bfloat16_rn(acc);
        sah[o] = hi;
        sal[o] = __float2bfloat16_rn(acc - __bfloat162float(hi));
        __syncwarp();
    }
}

// ---------------- multi-scale deformable sampling (writes planes) ----------------
__global__ void __launch_bounds__(256) deform_kernel(
    const float* __restrict__ offaw,
    const float* __restrict__ bbox, const float* __restrict__ value,
    const int* __restrict__ spatial, const int* __restrict__ lstart,
    __nv_bfloat16* __restrict__ cah, __nv_bfloat16* __restrict__ cal)
{
    __shared__ float s_w[8][32][4];
    __shared__ int   s_i[8][32][4];
    int bq = blockIdx.x;
    int b = bq / NQ, q = bq - b*NQ;
    int warp = threadIdx.x >> 5, lane = threadIdx.x & 31;

    const float* tok = offaw + (long)bq * 768;
    float a = tok[512 + warp*32 + lane];
    float m = a;
#pragma unroll
    for (int o = 16; o; o >>= 1) m = fmaxf(m, __shfl_xor_sync(0xffffffffu, m, o));
    float e = expf(a - m);
    float s = e;
#pragma unroll
    for (int o = 16; o; o >>= 1) s += __shfl_xor_sync(0xffffffffu, s, o);
    float p = e / s;

    float ox = tok[warp*64 + lane*2];
    float oy = tok[warp*64 + lane*2 + 1];
    const float* rb = bbox + ((long)q*BSZ + b)*4;
    float r0 = rb[0], r1 = rb[1], r2 = rb[2], r3 = rb[3];

    int lvl = lane >> 3;
    int H = spatial[lvl*2], W = spatial[lvl*2 + 1], ls = lstart[lvl];
    float Wf = (float)W, Hf = (float)H;
    float x = (r0 + ox*0.0625f*r2) * Wf - 0.5f;
    float y = (r1 + oy*0.0625f*r3) * Hf - 0.5f;
    float x0 = floorf(x), y0 = floorf(y);
    float fx = x - x0, fy = y - y0;

#pragma unroll
    for (int c = 0; c < 4; c++) {
        float xi = x0 + (float)(c & 1);
        float yi = y0 + (float)(c >> 1);
        float wgt = ((c & 1) ? fx : 1.f - fx) * ((c >> 1) ? fy : 1.f - fy);
        bool valid = (xi >= 0.f) && (xi < Wf) && (yi >= 0.f) && (yi < Hf);
        int xc = (int)fminf(fmaxf(xi, 0.f), Wf - 1.f);
        int yc = (int)fminf(fmaxf(yi, 0.f), Hf - 1.f);
        s_i[warp][lane][c] = ls + yc*W + xc;
        s_w[warp][lane][c] = valid ? wgt * p : 0.f;
    }
    __syncwarp();

    const float* vb = value + (long)b * STOT * DIM + warp*DH + lane;
    float acc = 0.f;
    for (int lp = 0; lp < 32; lp++) {
#pragma unroll
        for (int c = 0; c < 4; c++) {
            float wgt = s_w[warp][lp][c];
            if (wgt != 0.f)
                acc = fmaf(wgt, vb[(long)s_i[warp][lp][c] << 8], acc);
        }
    }
    long o = (long)bq*DIM + warp*DH + lane;
    __nv_bfloat16 hi = __float2bfloat16_rn(acc);
    cah[o] = hi;
    cal[o] = __float2bfloat16_rn(acc - __bfloat162float(hi));
}

// ---------------- host orchestration (single stream) ----------------
extern "C" void kernel_launch(void* const* d_in, const int* in_sizes, int n_in,
                              void* d_out, int out_size)
{
    const float* tgt        = (const float*)d_in[0];
    const float* qmask      = (const float*)d_in[1];
    const float* bbox       = (const float*)d_in[2];
    const float* memory     = (const float*)d_in[4];
    const float* in_proj_w  = (const float*)d_in[5];
    const float* in_proj_b  = (const float*)d_in[6];
    const float* out_sa_w   = (const float*)d_in[7];
    const float* out_sa_b   = (const float*)d_in[8];
    const float* norm2_g    = (const float*)d_in[9];
    const float* norm2_b    = (const float*)d_in[10];
    const float* value_w    = (const float*)d_in[11];
    const float* value_b    = (const float*)d_in[12];
    const float* off_w      = (const float*)d_in[13];
    const float* off_b      = (const float*)d_in[14];
    const float* aw_w       = (const float*)d_in[15];
    const float* aw_b       = (const float*)d_in[16];
    const float* out_ca_w   = (const float*)d_in[17];
    const float* out_ca_b   = (const float*)d_in[18];
    const float* norm1_g    = (const float*)d_in[19];
    const float* norm1_b    = (const float*)d_in[20];
    const float* lin1_w     = (const float*)d_in[21];
    const float* lin1_b     = (const float*)d_in[22];
    const float* lin2_w     = (const float*)d_in[23];
    const float* lin2_b     = (const float*)d_in[24];
    const float* norm3_g    = (const float*)d_in[25];
    const float* norm3_b    = (const float*)d_in[26];
    const unsigned char* pmask = (const unsigned char*)d_in[27];
    const int* spatial      = (const int*)d_in[28];
    const int* lstart       = (const int*)d_in[29];
    float* out = (float*)d_out;

    float *qhp,*khp,*vhp,*saout,*tgt2,*offb,*val,*caout,*tgt3,*f2;
    __nv_bfloat16 *wh,*wl,*qbh,*qbl,*tgh,*tgl,*sah,*sal,*q2h,*q2l,*t3h,*t3l,*f1h,*f1l,*cah,*cal;
    cudaGetSymbolAddress((void**)&qhp,   g_qh);
    cudaGetSymbolAddress((void**)&khp,   g_kh);
    cudaGetSymbolAddress((void**)&vhp,   g_vh);
    cudaGetSymbolAddress((void**)&saout, g_saout);
    cudaGetSymbolAddress((void**)&tgt2,  g_tgt2);
    cudaGetSymbolAddress((void**)&offb,  g_off);
    cudaGetSymbolAddress((void**)&val,   g_value);
    cudaGetSymbolAddress((void**)&caout, g_caout);
    cudaGetSymbolAddress((void**)&tgt3,  g_tgt3);
    cudaGetSymbolAddress((void**)&f2,    g_f2);
    cudaGetSymbolAddress((void**)&wh,    g_wh);
    cudaGetSymbolAddress((void**)&wl,    g_wl);
    cudaGetSymbolAddress((void**)&qbh,   g_qbh);
    cudaGetSymbolAddress((void**)&qbl,   g_qbl);
    cudaGetSymbolAddress((void**)&tgh,   g_tgh);
    cudaGetSymbolAddress((void**)&tgl,   g_tgl);
    cudaGetSymbolAddress((void**)&sah,   g_sah);
    cudaGetSymbolAddress((void**)&sal,   g_sal);
    cudaGetSymbolAddress((void**)&q2h,   g_q2h);
    cudaGetSymbolAddress((void**)&q2l,   g_q2l);
    cudaGetSymbolAddress((void**)&t3h,   g_t3h);
    cudaGetSymbolAddress((void**)&t3l,   g_t3l);
    cudaGetSymbolAddress((void**)&f1h,   g_f1h);
    cudaGetSymbolAddress((void**)&f1l,   g_f1l);
    cudaGetSymbolAddress((void**)&cah,   g_cah);
    cudaGetSymbolAddress((void**)&cal,   g_cal);

    // 0) converts: weights (cheap) + tgt/qbuf planes. NO memory convert.
    {
        WDesc d;
        d.src[0]=in_proj_w; d.off[0]=W_INPROJ; d.n4[0]=196608/4;
        d.src[1]=out_sa_w;  d.off[1]=W_OUTSA;  d.n4[1]=65536/4;
        d.src[2]=value_w;   d.off[2]=W_VALUE;  d.n4[2]=65536/4;
        d.src[3]=off_w;     d.off[3]=W_OFF;    d.n4[3]=131072/4;
        d.src[4]=aw_w;      d.off[4]=W_AW;     d.n4[4]=65536/4;
        d.src[5]=out_ca_w;  d.off[5]=W_OUTCA;  d.n4[5]=65536/4;
        d.src[6]=lin1_w;    d.off[6]=W_LIN1;   d.n4[6]=262144/4;
        d.src[7]=lin2_w;    d.off[7]=W_LIN2;   d.n4[7]=262144/4;
        dim3 g((262144/4 + 255)/256, 8);
        cvt_w_kernel<<<g, 256>>>(d, wh, wl);
    }
    add_cvt2_kernel<<<TOKF/4/256, 256>>>(tgt, qmask, qbh, qbl, tgh, tgl);

    // 1) value projection: fp32 memory x plane weights (batched over BS)
    {
        dim3 vg(2, (STOT + 63) / 64, BSZ);
        cudaFuncSetAttribute(mma_val, cudaFuncAttributeMaxDynamicSharedMemorySize, 2*VSTG);
        mma_val<<<vg, 256, 2*VSTG>>>(memory, BSZ*DIM, 256,
                                     wh+W_VALUE, wl+W_VALUE, DIM, value_b,
                                     val, (long)STOT*DIM, DIM, STOT, DIM, pmask, STOT);
    }

    // 2) Q+K merged (N=512), then V — plane-plane
    launch_pp(2, qbh, qbl, DIM, wh+W_INPROJ, wl+W_INPROJ, DIM, in_proj_b,
              nullptr, nullptr, nullptr, 0,
              qhp, khp, nullptr, nullptr, 0, NTOK, 512, DIM);
    launch_pp(2, tgh, tgl, DIM, wh+W_INPROJ+512*256, wl+W_INPROJ+512*256, DIM, in_proj_b+512,
              nullptr, nullptr, nullptr, 0,
              vhp, vhp, nullptr, nullptr, 0, NTOK, 256, DIM);

    // 3) fused self-attention -> planes
    {
        int smem = (300*36*2 + 150*32 + 8*320) * 4;
        cudaFuncSetAttribute(attn_kernel, cudaFuncAttributeMaxDynamicSharedMemorySize, smem);
        attn_kernel<<<128, 256, smem>>>(qhp, khp, vhp, sah, sal);
    }

    // 4) self-attn out-proj + LN (norm2)
    launch_pp(0, sah, sal, DIM, wh+W_OUTSA, wl+W_OUTSA, DIM, out_sa_b,
              nullptr, nullptr, nullptr, 0,
              saout, nullptr, nullptr, nullptr, DIM, NTOK, 256, DIM);
    ln_kernel<<<NTOK/8, 256>>>(tgt, saout, 0, norm2_g, norm2_b, tgt2, nullptr, nullptr);

    // 5) query2 planes
    permadd_cvt_kernel<<<(TOKF/4 + 255)/256, 256>>>(tgt2, qmask, q2h, q2l);

    // 6) offsets + aw logits merged (N=768, split at 512)
    launch_pp(0, q2h, q2l, DIM, wh+W_OFF, wl+W_OFF, DIM, off_b,
              wh+W_AW, wl+W_AW, aw_b, 512,
              offb, nullptr, nullptr, nullptr, 768, NTOK, 768, DIM);

    // 7) deformable sampling -> planes
    deform_kernel<<<NTOK, 256>>>(offb, bbox, val, spatial, lstart, cah, cal);

    // 8) cross-attn out-proj + LN (norm1) -> tgt3 + planes
    launch_pp(0, cah, cal, DIM, wh+W_OUTCA, wl+W_OUTCA, DIM, out_ca_b,
              nullptr, nullptr, nullptr, 0,
              caout, nullptr, nullptr, nullptr, DIM, NTOK, 256, DIM);
    ln_kernel<<<NTOK/8, 256>>>(tgt2, caout, 1, norm1_g, norm1_b, tgt3, t3h, t3l);

    // 9) FFN + final LN -> d_out
    launch_pp(1, t3h, t3l, DIM, wh+W_LIN1, wl+W_LIN1, DIM, lin1_b,
              nullptr, nullptr, nullptr, 0,
              nullptr, nullptr, f1h, f1l, DFF, NTOK, DFF, DIM);
    launch_pp(0, f1h, f1l, DFF, wh+W_LIN2, wl+W_LIN2, DFF, lin2_b,
              nullptr, nullptr, nullptr, 0,
              f2, nullptr, nullptr, nullptr, DIM, NTOK, 256, DFF);
    ln_kernel<<<NTOK/8, 256>>>(tgt3, f2, 0, norm3_g, norm3_b, out, nullptr, nullptr);
}

// round 13
// speedup vs baseline: 1.2701x; 1.1625x over previous
#include <cuda_runtime.h>
#include <cuda_fp16.h>
#include <math.h>
#include <cstdint>

// ---------------- problem constants ----------------
#define NQ   300
#define BSZ  8
#define DIM  256
#define NH   8
#define DH   32
#define DFF  1024
#define STOT 13294
#define NTOK (NQ*BSZ)          // 2400
#define TOKF (NTOK*DIM)        // 614400

// weight plane offsets (elements)
#define W_INPROJ 0L
#define W_OUTSA  196608L
#define W_VALUE  262144L
#define W_OFF    327680L
#define W_AW     458752L
#define W_OUTCA  524288L
#define W_LIN1   589824L
#define W_LIN2   851968L
#define W_TOTAL  1114112L

// ---------------- scratch (static device globals; no allocations) ----------------
__device__ float g_qbuf [TOKF];
__device__ float g_qh   [TOKF];
__device__ float g_kh   [TOKF];
__device__ float g_vh   [TOKF];
__device__ float g_sain [TOKF];
__device__ float g_saout[TOKF];
__device__ float g_tgt2 [TOKF];
__device__ float g_q2   [TOKF];
__device__ float g_off  [NTOK*768];
__device__ float g_value[(long)BSZ*STOT*DIM];
__device__ float g_cain [TOKF];
__device__ float g_caout[TOKF];
__device__ float g_tgt3 [TOKF];
__device__ float g_f1   [NTOK*DFF];
__device__ float g_f2   [TOKF];
__device__ __half g_wh[W_TOTAL], g_wl[W_TOTAL];   // weight fp16 hi/lo planes

// ---------------- helpers ----------------
__device__ __forceinline__ uint32_t smem_u32(const void* p) {
    uint32_t a;
    asm("{ .reg .u64 t; cvta.to.shared.u64 t, %1; cvt.u32.u64 %0, t; }" : "=r"(a) : "l"(p));
    return a;
}
__device__ __forceinline__ unsigned pkh(__half a, __half b) {
    __half2 t = __halves2half2(a, b);
    return *reinterpret_cast<unsigned*>(&t);
}
__device__ __forceinline__ void mma_f16(float* d, const uint32_t* a, uint32_t b0, uint32_t b1) {
    asm volatile(
        "mma.sync.aligned.m16n8k16.row.col.f32.f16.f16.f32 "
        "{%0,%1,%2,%3}, {%4,%5,%6,%7}, {%8,%9}, {%0,%1,%2,%3};"
        : "+f"(d[0]), "+f"(d[1]), "+f"(d[2]), "+f"(d[3])
        : "r"(a[0]), "r"(a[1]), "r"(a[2]), "r"(a[3]), "r"(b0), "r"(b1));
}
__device__ __forceinline__ void ldmx4(uint32_t* r, uint32_t addr) {
    asm volatile("ldmatrix.sync.aligned.m8n8.x4.shared.b16 {%0,%1,%2,%3}, [%4];"
                 : "=r"(r[0]), "=r"(r[1]), "=r"(r[2]), "=r"(r[3]) : "r"(addr));
}
// A: fp32x4 -> fp16x4 (single precision term)
__device__ __forceinline__ uint2 cvt_a(float4 v) {
    return make_uint2(pkh(__float2half_rn(v.x), __float2half_rn(v.y)),
                      pkh(__float2half_rn(v.z), __float2half_rn(v.w)));
}

// ============ fp16 2-term GEMM: C = A(MxK fp32) * Wplanes(NxK)^T + bias ============
// A converted in-register to single fp16; W pre-split fp16 hi/lo planes.
// D = A*Whi + A*Wlo  (error ~ A fp16 quantization ~1.5e-4 RMS).
// CTA 64x128, 256 thr, 8 warps of 32x32. K chunks 32, 2-stage ping-pong.
// Stage 20480 B: A[64x32] @0 (4KB), Bhi[128x32] @4096 (8KB), Blo @12288 (8KB).
// Rows 64B; 16B chunks swizzled c' = c ^ ((row>>1)&3).
// EPI: 0 plain, 1 relu, 2 head-permute (C2 for n>=256), 3 pad-mask zero (batched).
#define STG 20480

template<int EPI>
__global__ void __launch_bounds__(256, 2) mma_gemm(
    const float* __restrict__ A, int lda, long aOff,
    const __half* __restrict__ Bhi, const __half* __restrict__ Blo, int ldw,
    const float* __restrict__ bias,
    const __half* W2hi, const __half* W2lo, const float* bias2, int Nsplit,
    float* __restrict__ C, float* __restrict__ C2, int ldc, long cOff,
    int M, int K,
    const unsigned char* __restrict__ mask, long mOff)
{
    extern __shared__ __align__(128) unsigned char sm[];
    const uint32_t sb = smem_u32(sm);
    const int tid = threadIdx.x;
    const int bm = blockIdx.y * 64;
    const int bn = blockIdx.x * 128;
    A += (long)blockIdx.z * aOff;
    C += (long)blockIdx.z * cOff;
    if (Nsplit && bn >= Nsplit) {
        Bhi = W2hi - (long)Nsplit * ldw;
        Blo = W2lo - (long)Nsplit * ldw;
        bias = bias2 - Nsplit;
    }

    const int warp = tid >> 5, lane = tid & 31;
    const int wm = warp & 1, wn = warp >> 1;

    // A prefetch: 64 rows x 32 k fp32 = 512 float4 (2/thr)
    int arow[2], akq[2]; bool agd[2]; const float* aptr[2]; uint32_t asw[2];
#pragma unroll
    for (int j = 0; j < 2; j++) {
        int i = tid + j * 256;
        arow[j] = i >> 3; akq[j] = i & 7;
        agd[j] = (bm + arow[j]) < M;
        aptr[j] = A + (long)(bm + arow[j]) * lda + akq[j] * 4;
        asw[j] = (uint32_t)(arow[j] * 64 + (((akq[j] >> 1) ^ ((arow[j] >> 1) & 3)) << 4) + (akq[j] & 1) * 8);
    }
    // B planes: 128 rows x 32 halves = 512 uint4 per plane (2/thr per plane)
    int brow[2], bch[2]; const __half *bhp[2], *blp[2]; uint32_t bsw[2];
#pragma unroll
    for (int j = 0; j < 2; j++) {
        int i = tid + j * 256;
        brow[j] = i >> 2; bch[j] = i & 3;
        bhp[j] = Bhi + (long)(bn + brow[j]) * ldw + bch[j] * 8;
        blp[j] = Blo + (long)(bn + brow[j]) * ldw + bch[j] * 8;
        bsw[j] = (uint32_t)(brow[j] * 64 + ((bch[j] ^ ((brow[j] >> 1) & 3)) << 4));
    }

    float acc[2][4][4];
#pragma unroll
    for (int mt = 0; mt < 2; mt++)
#pragma unroll
        for (int nt = 0; nt < 4; nt++)
#pragma unroll
            for (int r = 0; r < 4; r++) acc[mt][nt][r] = 0.f;

    const int nk = K >> 5;
    float4 av[2];
    uint4 bh[2], bl[2];

    // load + stage chunk 0
#pragma unroll
    for (int j = 0; j < 2; j++) {
        av[j] = agd[j] ? *(const float4*)(aptr[j]) : make_float4(0.f,0.f,0.f,0.f);
        bh[j] = *(const uint4*)(bhp[j]);
        bl[j] = *(const uint4*)(blp[j]);
    }
#pragma unroll
    for (int j = 0; j < 2; j++) {
        *(uint2*)(sm + asw[j]) = cvt_a(av[j]);
        *(uint4*)(sm + 4096 + bsw[j])  = bh[j];
        *(uint4*)(sm + 12288 + bsw[j]) = bl[j];
    }
    __syncthreads();

    for (int kc = 0; kc < nk; kc++) {
        const int st = kc & 1;
        const uint32_t so = sb + (uint32_t)(st * STG);
        const bool more = (kc + 1) < nk;

        // issue next-chunk gmem loads (latency hidden under MMA)
        if (more) {
            int kb = (kc + 1) * 32;
#pragma unroll
            for (int j = 0; j < 2; j++) {
                av[j] = agd[j] ? *(const float4*)(aptr[j] + kb) : make_float4(0.f,0.f,0.f,0.f);
                bh[j] = *(const uint4*)(bhp[j] + kb);
                bl[j] = *(const uint4*)(blp[j] + kb);
            }
        }

        // compute: 2 k16 steps, warp tile 32x32
#pragma unroll
        for (int ks = 0; ks < 2; ks++) {
            uint32_t af[2][4];
#pragma unroll
            for (int mt = 0; mt < 2; mt++) {
                int row = wm * 32 + mt * 16 + (lane & 7) + ((lane >> 3) & 1) * 8;
                int c = 2 * ks + (lane >> 4);
                uint32_t off = (uint32_t)(row * 64 + ((c ^ ((row >> 1) & 3)) << 4));
                ldmx4(af[mt], so + off);
            }
            uint32_t bhf[4][2], blf[4][2];
#pragma unroll
            for (int np = 0; np < 2; np++) {
                int row = wn * 32 + np * 16 + (lane & 7) + (lane >> 4) * 8;
                int c = 2 * ks + ((lane >> 3) & 1);
                uint32_t off = (uint32_t)(row * 64 + ((c ^ ((row >> 1) & 3)) << 4));
                uint32_t t[4];
                ldmx4(t, so + 4096 + off);
                bhf[2*np][0] = t[0]; bhf[2*np][1] = t[1];
                bhf[2*np+1][0] = t[2]; bhf[2*np+1][1] = t[3];
                ldmx4(t, so + 12288 + off);
                blf[2*np][0] = t[0]; blf[2*np][1] = t[1];
                blf[2*np+1][0] = t[2]; blf[2*np+1][1] = t[3];
            }
#pragma unroll
            for (int mt = 0; mt < 2; mt++)
#pragma unroll
                for (int nt = 0; nt < 4; nt++) {
                    mma_f16(acc[mt][nt], af[mt], bhf[nt][0], bhf[nt][1]);
                    mma_f16(acc[mt][nt], af[mt], blf[nt][0], blf[nt][1]);
                }
        }

        // stage next chunk into other buffer
        if (more) {
            const uint32_t po = (uint32_t)((st ^ 1) * STG);
#pragma unroll
            for (int j = 0; j < 2; j++) {
                *(uint2*)(sm + po + asw[j]) = cvt_a(av[j]);
                *(uint4*)(sm + po + 4096 + bsw[j])  = bh[j];
                *(uint4*)(sm + po + 12288 + bsw[j]) = bl[j];
            }
        }
        __syncthreads();
    }

    // ---------------- epilogue ----------------
#pragma unroll
    for (int mt = 0; mt < 2; mt++) {
        int r0 = bm + wm * 32 + mt * 16 + (lane >> 2);
#pragma unroll
        for (int nt = 0; nt < 4; nt++) {
            int n0 = bn + wn * 32 + nt * 8 + (lane & 3) * 2;
            float b0 = bias[n0], b1 = bias[n0 + 1];
#pragma unroll
            for (int half = 0; half < 2; half++) {
                int r = r0 + half * 8;
                if (r >= M) continue;
                float v0 = acc[mt][nt][half * 2 + 0] + b0;
                float v1 = acc[mt][nt][half * 2 + 1] + b1;
                if (EPI == 1) { v0 = fmaxf(v0, 0.f); v1 = fmaxf(v1, 0.f); }
                if (EPI == 3) {
                    if (mask[(long)blockIdx.z * mOff + r]) { v0 = 0.f; v1 = 0.f; }
                }
                if (EPI == 2) {
                    float* base = C; int nn = n0;
                    if (C2 && nn >= 256) { base = C2; nn -= 256; }
                    int q = r >> 3, bb = r & 7, hh = nn >> 5, d = nn & 31;
                    float* p = base + (((long)(bb * NH + hh)) * NQ + q) * DH + d;
                    p[0] = v0; p[1] = v1;
                } else {
                    float* p = C + (long)r * ldc + n0;
                    p[0] = v0; p[1] = v1;
                }
            }
        }
    }
}

static inline void launch_mma(int epi,
    const float* A, int lda, long aOff,
    const __half* Bhi, const __half* Blo, int ldw, const float* bias,
    const __half* W2hi, const __half* W2lo, const float* bias2, int Nsplit,
    float* C, float* C2, int ldc, long cOff,
    int M, int N, int K, int nz,
    const unsigned char* mask, long mOff)
{
    dim3 grid(N / 128, (M + 63) / 64, nz);
    const int SMEM = 2 * STG;
#define LM(E) do { \
    cudaFuncSetAttribute(mma_gemm<E>, cudaFuncAttributeMaxDynamicSharedMemorySize, SMEM); \
    mma_gemm<E><<<grid,256,SMEM>>>(A,lda,aOff,Bhi,Blo,ldw,bias,W2hi,W2lo,bias2,Nsplit, \
                                   C,C2,ldc,cOff,M,K,mask,mOff); } while (0)
    switch (epi) {
        case 0: LM(0); break;
        case 1: LM(1); break;
        case 2: LM(2); break;
        case 3: LM(3); break;
    }
#undef LM
}

// ---------------- weight convert: fp32 -> fp16 hi/lo planes ----------------
struct WDesc { const float* src[8]; long off[8]; int n4[8]; };
__global__ void cvt_w_kernel(WDesc d, __half* __restrict__ hi, __half* __restrict__ lo)
{
    int w = blockIdx.y;
    int i = blockIdx.x * blockDim.x + threadIdx.x;
    if (i >= d.n4[w]) return;
    float4 v = ((const float4*)d.src[w])[i];
    __half h0 = __float2half_rn(v.x), h1 = __float2half_rn(v.y);
    __half h2 = __float2half_rn(v.z), h3 = __float2half_rn(v.w);
    __half l0 = __float2half_rn(v.x - __half2float(h0));
    __half l1 = __float2half_rn(v.y - __half2float(h1));
    __half l2 = __float2half_rn(v.z - __half2float(h2));
    __half l3 = __float2half_rn(v.w - __half2float(h3));
    ((uint2*)(hi + d.off[w]))[i] = make_uint2(pkh(h0, h1), pkh(h2, h3));
    ((uint2*)(lo + d.off[w]))[i] = make_uint2(pkh(l0, l1), pkh(l2, l3));
}

// ---------------- elementwise ----------------
__global__ void add_kernel(const float* __restrict__ a, const float* __restrict__ b,
                           float* __restrict__ o, int n4)
{
    int i = blockIdx.x * blockDim.x + threadIdx.x;
    if (i < n4) {
        float4 x = ((const float4*)a)[i], y = ((const float4*)b)[i];
        ((float4*)o)[i] = make_float4(x.x+y.x, x.y+y.y, x.z+y.z, x.w+y.w);
    }
}

__global__ void permadd_kernel(const float* __restrict__ t2, const float* __restrict__ msk,
                               float* __restrict__ q2)
{
    int i = blockIdx.x * 256 + threadIdx.x;   // over TOKF/4 float4s
    if (i >= TOKF/4) return;
    int d4 = i & 63;
    int t = i >> 6;
    int q = t >> 3, b = t & 7;
    float4 x = ((const float4*)t2)[i], y = ((const float4*)msk)[i];
    ((float4*)q2)[((long)(b*NQ + q) << 6) + d4] = make_float4(x.x+y.x, x.y+y.y, x.z+y.z, x.w+y.w);
}

// ---------------- residual + layernorm ----------------
__global__ void __launch_bounds__(256) ln_kernel(
    const float* __restrict__ A, const float* __restrict__ B, int bBQ,
    const float* __restrict__ g, const float* __restrict__ be,
    float* __restrict__ out)
{
    int t = blockIdx.x * 8 + (threadIdx.x >> 5);
    int lane = threadIdx.x & 31;
    if (t >= NTOK) return;
    const float* ap = A + (long)t * DIM + lane*8;
    long bo;
    if (bBQ) { int q = t >> 3, b = t & 7; bo = (long)(b*NQ + q) * DIM; }
    else     { bo = (long)t * DIM; }
    const float* bp = B + bo + lane*8;

    float4 x0 = *(const float4*)ap,      x1 = *(const float4*)(ap + 4);
    float4 y0 = *(const float4*)bp,      y1 = *(const float4*)(bp + 4);
    float v[8] = {x0.x+y0.x, x0.y+y0.y, x0.z+y0.z, x0.w+y0.w,
                  x1.x+y1.x, x1.y+y1.y, x1.z+y1.z, x1.w+y1.w};
    float s = 0.f;
#pragma unroll
    for (int i = 0; i < 8; i++) s += v[i];
#pragma unroll
    for (int o = 16; o; o >>= 1) s += __shfl_xor_sync(0xffffffffu, s, o);
    float mu = s * (1.f/256.f);
    float s2 = 0.f;
#pragma unroll
    for (int i = 0; i < 8; i++) { float d = v[i] - mu; s2 += d*d; }
#pragma unroll
    for (int o = 16; o; o >>= 1) s2 += __shfl_xor_sync(0xffffffffu, s2, o);
    float inv = rsqrtf(s2 * (1.f/256.f) + 1e-5f);
    int c0 = lane*8;
    float* op = out + (long)t * DIM + c0;
#pragma unroll
    for (int i = 0; i < 8; i++)
        op[i] = (v[i] - mu) * inv * g[c0+i] + be[c0+i];
}

// ---------------- fused self-attention ----------------
__global__ void __launch_bounds__(256) attn_kernel(
    const float* __restrict__ qh, const float* __restrict__ kh,
    const float* __restrict__ vh, float* __restrict__ sa_in)
{
    extern __shared__ float smf[];
    const int bh   = blockIdx.x >> 1;
    const int half = blockIdx.x & 1;
    const int b = bh >> 3, h = bh & 7;
    float* Ks = smf;
    float* Vs = Ks + 300*36;
    float* Qs = Vs + 300*36;
    float* Ps = Qs + 150*32;

    const float scale = 0.17677669529663687f;
    const float* Kg = kh + (long)bh * NQ * DH;
    const float* Vg = vh + (long)bh * NQ * DH;
    const float* Qg = qh + (long)bh * NQ * DH + (long)half * 150 * DH;
    const int tid = threadIdx.x;

    for (int i = tid; i < 2400; i += 256) {
        int r = i >> 3, c4 = (i & 7) << 2;
        float4 kv = *(const float4*)(Kg + r*32 + c4);
        float4 vv = *(const float4*)(Vg + r*32 + c4);
        *(float4*)(Ks + r*36 + c4) = kv;
        *(float4*)(Vs + r*36 + c4) = vv;
    }
    for (int i = tid; i < 1200; i += 256) {
        int r = i >> 3, c4 = (i & 7) << 2;
        float4 qv = *(const float4*)(Qg + r*32 + c4);
        qv.x *= scale; qv.y *= scale; qv.z *= scale; qv.w *= scale;
        *(float4*)(Qs + r*32 + c4) = qv;
    }
    __syncthreads();

    const int warp = tid >> 5, lane = tid & 31;
    float* Pw = Ps + warp * 320;

    for (int q = warp; q < 150; q += 8) {
        float4 qr[8];
#pragma unroll
        for (int d4 = 0; d4 < 8; d4++) qr[d4] = *(const float4*)(Qs + q*32 + d4*4);

        float sc[10];
#pragma unroll
        for (int j = 0; j < 10; j++) {
            int k = j*32 + lane;
            float s = -1e30f;
            if (k < 300) {
                s = 0.f;
#pragma unroll
                for (int d4 = 0; d4 < 8; d4++) {
                    float4 kv = *(const float4*)(Ks + k*36 + d4*4);
                    s = fmaf(qr[d4].x, kv.x, s);
                    s = fmaf(qr[d4].y, kv.y, s);
                    s = fmaf(qr[d4].z, kv.z, s);
                    s = fmaf(qr[d4].w, kv.w, s);
                }
            }
            sc[j] = s;
        }
        float m = sc[0];
#pragma unroll
        for (int j = 1; j < 10; j++) m = fmaxf(m, sc[j]);
#pragma unroll
        for (int o = 16; o; o >>= 1) m = fmaxf(m, __shfl_xor_sync(0xffffffffu, m, o));
        float sum = 0.f;
#pragma unroll
        for (int j = 0; j < 10; j++) { sc[j] = expf(sc[j] - m); sum += sc[j]; }
#pragma unroll
        for (int o = 16; o; o >>= 1) sum += __shfl_xor_sync(0xffffffffu, sum, o);
        float inv = 1.f / sum;
#pragma unroll
        for (int j = 0; j < 10; j++) Pw[j*32 + lane] = sc[j] * inv;
        __syncwarp();

        float acc = 0.f;
#pragma unroll 4
        for (int k = 0; k < 300; k++)
            acc = fmaf(Pw[k], Vs[k*36 + lane], acc);

        int qg = half*150 + q;
        sa_in[((long)(qg*BSZ + b)) * DIM + h*DH + lane] = acc;
        __syncwarp();
    }
}

// ---------------- multi-scale deformable sampling ----------------
__global__ void __launch_bounds__(256) deform_kernel(
    const float* __restrict__ offaw,
    const float* __restrict__ bbox, const float* __restrict__ value,
    const int* __restrict__ spatial, const int* __restrict__ lstart,
    float* __restrict__ ca_in)
{
    __shared__ float s_w[8][32][4];
    __shared__ int   s_i[8][32][4];
    int bq = blockIdx.x;
    int b = bq / NQ, q = bq - b*NQ;
    int warp = threadIdx.x >> 5, lane = threadIdx.x & 31;

    const float* tok = offaw + (long)bq * 768;
    float a = tok[512 + warp*32 + lane];
    float m = a;
#pragma unroll
    for (int o = 16; o; o >>= 1) m = fmaxf(m, __shfl_xor_sync(0xffffffffu, m, o));
    float e = expf(a - m);
    float s = e;
#pragma unroll
    for (int o = 16; o; o >>= 1) s += __shfl_xor_sync(0xffffffffu, s, o);
    float p = e / s;

    float ox = tok[warp*64 + lane*2];
    float oy = tok[warp*64 + lane*2 + 1];
    const float* rb = bbox + ((long)q*BSZ + b)*4;
    float r0 = rb[0], r1 = rb[1], r2 = rb[2], r3 = rb[3];

    int lvl = lane >> 3;
    int H = spatial[lvl*2], W = spatial[lvl*2 + 1], ls = lstart[lvl];
    float Wf = (float)W, Hf = (float)H;
    float x = (r0 + ox*0.0625f*r2) * Wf - 0.5f;
    float y = (r1 + oy*0.0625f*r3) * Hf - 0.5f;
    float x0 = floorf(x), y0 = floorf(y);
    float fx = x - x0, fy = y - y0;

#pragma unroll
    for (int c = 0; c < 4; c++) {
        float xi = x0 + (float)(c & 1);
        float yi = y0 + (float)(c >> 1);
        float wgt = ((c & 1) ? fx : 1.f - fx) * ((c >> 1) ? fy : 1.f - fy);
        bool valid = (xi >= 0.f) && (xi < Wf) && (yi >= 0.f) && (yi < Hf);
        int xc = (int)fminf(fmaxf(xi, 0.f), Wf - 1.f);
        int yc = (int)fminf(fmaxf(yi, 0.f), Hf - 1.f);
        s_i[warp][lane][c] = ls + yc*W + xc;
        s_w[warp][lane][c] = valid ? wgt * p : 0.f;
    }
    __syncwarp();

    const float* vb = value + (long)b * STOT * DIM + warp*DH + lane;
    float acc = 0.f;
    for (int lp = 0; lp < 32; lp++) {
#pragma unroll
        for (int c = 0; c < 4; c++) {
            float wgt = s_w[warp][lp][c];
            if (wgt != 0.f)
                acc = fmaf(wgt, vb[(long)s_i[warp][lp][c] << 8], acc);
        }
    }
    ca_in[(long)bq*DIM + warp*DH + lane] = acc;
}

// ---------------- host orchestration (single stream; no allocations) ----------------
extern "C" void kernel_launch(void* const* d_in, const int* in_sizes, int n_in,
                              void* d_out, int out_size)
{
    const float* tgt        = (const float*)d_in[0];
    const float* qmask      = (const float*)d_in[1];
    const float* bbox       = (const float*)d_in[2];
    const float* memory     = (const float*)d_in[4];
    const float* in_proj_w  = (const float*)d_in[5];
    const float* in_proj_b  = (const float*)d_in[6];
    const float* out_sa_w   = (const float*)d_in[7];
    const float* out_sa_b   = (const float*)d_in[8];
    const float* norm2_g    = (const float*)d_in[9];
    const float* norm2_b    = (const float*)d_in[10];
    const float* value_w    = (const float*)d_in[11];
    const float* value_b    = (const float*)d_in[12];
    const float* off_w      = (const float*)d_in[13];
    const float* off_b      = (const float*)d_in[14];
    const float* aw_w       = (const float*)d_in[15];
    const float* aw_b       = (const float*)d_in[16];
    const float* out_ca_w   = (const float*)d_in[17];
    const float* out_ca_b   = (const float*)d_in[18];
    const float* norm1_g    = (const float*)d_in[19];
    const float* norm1_b    = (const float*)d_in[20];
    const float* lin1_w     = (const float*)d_in[21];
    const float* lin1_b     = (const float*)d_in[22];
    const float* lin2_w     = (const float*)d_in[23];
    const float* lin2_b     = (const float*)d_in[24];
    const float* norm3_g    = (const float*)d_in[25];
    const float* norm3_b    = (const float*)d_in[26];
    const unsigned char* pmask = (const unsigned char*)d_in[27];
    const int* spatial      = (const int*)d_in[28];
    const int* lstart       = (const int*)d_in[29];
    float* out = (float*)d_out;

    float *qbuf,*qh,*kh,*vh,*sain,*saout,*tgt2,*q2,*offb,*val,*cain,*caout,*tgt3,*f1,*f2;
    __half *wh,*wl;
    cudaGetSymbolAddress((void**)&qbuf,  g_qbuf);
    cudaGetSymbolAddress((void**)&qh,    g_qh);
    cudaGetSymbolAddress((void**)&kh,    g_kh);
    cudaGetSymbolAddress((void**)&vh,    g_vh);
    cudaGetSymbolAddress((void**)&sain,  g_sain);
    cudaGetSymbolAddress((void**)&saout, g_saout);
    cudaGetSymbolAddress((void**)&tgt2,  g_tgt2);
    cudaGetSymbolAddress((void**)&q2,    g_q2);
    cudaGetSymbolAddress((void**)&offb,  g_off);
    cudaGetSymbolAddress((void**)&val,   g_value);
    cudaGetSymbolAddress((void**)&cain,  g_cain);
    cudaGetSymbolAddress((void**)&caout, g_caout);
    cudaGetSymbolAddress((void**)&tgt3,  g_tgt3);
    cudaGetSymbolAddress((void**)&f1,    g_f1);
    cudaGetSymbolAddress((void**)&f2,    g_f2);
    cudaGetSymbolAddress((void**)&wh,    g_wh);
    cudaGetSymbolAddress((void**)&wl,    g_wl);

    // 0) weight planes (fp16 hi/lo) — one cheap kernel
    {
        WDesc d;
        d.src[0]=in_proj_w; d.off[0]=W_INPROJ; d.n4[0]=196608/4;
        d.src[1]=out_sa_w;  d.off[1]=W_OUTSA;  d.n4[1]=65536/4;
        d.src[2]=value_w;   d.off[2]=W_VALUE;  d.n4[2]=65536/4;
        d.src[3]=off_w;     d.off[3]=W_OFF;    d.n4[3]=131072/4;
        d.src[4]=aw_w;      d.off[4]=W_AW;     d.n4[4]=65536/4;
        d.src[5]=out_ca_w;  d.off[5]=W_OUTCA;  d.n4[5]=65536/4;
        d.src[6]=lin1_w;    d.off[6]=W_LIN1;   d.n4[6]=262144/4;
        d.src[7]=lin2_w;    d.off[7]=W_LIN2;   d.n4[7]=262144/4;
        dim3 g((262144/4 + 255)/256, 8);
        cvt_w_kernel<<<g, 256>>>(d, wh, wl);
    }

    // 1) q = tgt + query_mask
    add_kernel<<<TOKF/4/256, 256>>>(tgt, qmask, qbuf, TOKF/4);

    // 2) value projection over memory (batched over BS), pad-mask epilogue
    launch_mma(3, memory, BSZ*DIM, 256, wh+W_VALUE, wl+W_VALUE, DIM, value_b,
               nullptr, nullptr, nullptr, 0,
               val, nullptr, DIM, (long)STOT*DIM,
               STOT, DIM, DIM, BSZ, pmask, STOT);

    // 3) Q+K merged (N=512), then V
    launch_mma(2, qbuf, DIM, 0, wh+W_INPROJ, wl+W_INPROJ, DIM, in_proj_b,
               nullptr, nullptr, nullptr, 0,
               qh, kh, 0, 0, NTOK, 512, DIM, 1, nullptr, 0);
    launch_mma(2, tgt, DIM, 0, wh+W_INPROJ+512*256, wl+W_INPROJ+512*256, DIM, in_proj_b+512,
               nullptr, nullptr, nullptr, 0,
               vh, nullptr, 0, 0, NTOK, 256, DIM, 1, nullptr, 0);

    // 4) fused self-attention
    {
        int smem = (300*36*2 + 150*32 + 8*320) * 4;
        cudaFuncSetAttribute(attn_kernel, cudaFuncAttributeMaxDynamicSharedMemorySize, smem);
        attn_kernel<<<128, 256, smem>>>(qh, kh, vh, sain);
    }

    // 5) self-attn out-proj + residual LN (norm2)
    launch_mma(0, sain, DIM, 0, wh+W_OUTSA, wl+W_OUTSA, DIM, out_sa_b,
               nullptr, nullptr, nullptr, 0,
               saout, nullptr, DIM, 0, NTOK, DIM, DIM, 1, nullptr, 0);
    ln_kernel<<<NTOK/8, 256>>>(tgt, saout, 0, norm2_g, norm2_b, tgt2);

    // 6) query2 = (tgt2 + mask) in (b,q,d) layout
    permadd_kernel<<<(TOKF/4 + 255)/256, 256>>>(tgt2, qmask, q2);

    // 7) offsets + aw logits merged (N=768, split at 512)
    launch_mma(0, q2, DIM, 0, wh+W_OFF, wl+W_OFF, DIM, off_b,
               wh+W_AW, wl+W_AW, aw_b, 512,
               offb, nullptr, 768, 0, NTOK, 768, DIM, 1, nullptr, 0);

    // 8) deformable sampling
    deform_kernel<<<NTOK, 256>>>(offb, bbox, val, spatial, lstart, cain);

    // 9) cross-attn out-proj + residual LN (norm1)
    launch_mma(0, cain, DIM, 0, wh+W_OUTCA, wl+W_OUTCA, DIM, out_ca_b,
               nullptr, nullptr, nullptr, 0,
               caout, nullptr, DIM, 0, NTOK, DIM, DIM, 1, nullptr, 0);
    ln_kernel<<<NTOK/8, 256>>>(tgt2, caout, 1, norm1_g, norm1_b, tgt3);

    // 10) FFN + final LN (norm3) -> d_out
    launch_mma(1, tgt3, DIM, 0, wh+W_LIN1, wl+W_LIN1, DIM, lin1_b,
               nullptr, nullptr, nullptr, 0,
               f1, nullptr, DFF, 0, NTOK, DFF, DIM, 1, nullptr, 0);
    launch_mma(0, f1, DFF, 0, wh+W_LIN2, wl+W_LIN2, DFF, lin2_b,
               nullptr, nullptr, nullptr, 0,
               f2, nullptr, DIM, 0, NTOK, DIM, DFF, 1, nullptr, 0);
    ln_kernel<<<NTOK/8, 256>>>(tgt3, f2, 0, norm3_g, norm3_b, out);
}

// round 14
// speedup vs baseline: 1.3836x; 1.0893x over previous
#include <cuda_runtime.h>
#include <cuda_fp16.h>
#include <math.h>
#include <cstdint>

// ---------------- problem constants ----------------
#define NQ   300
#define BSZ  8
#define DIM  256
#define NH   8
#define DH   32
#define DFF  1024
#define STOT 13294
#define NTOK (NQ*BSZ)          // 2400
#define TOKF (NTOK*DIM)        // 614400

// weight plane offsets (elements)
#define W_INPROJ 0L
#define W_OUTSA  196608L
#define W_VALUE  262144L
#define W_OFF    327680L
#define W_AW     458752L
#define W_OUTCA  524288L
#define W_LIN1   589824L
#define W_LIN2   851968L
#define W_TOTAL  1114112L

// ---------------- scratch (static device globals; no allocations) ----------------
__device__ float g_qbuf [TOKF];
__device__ float g_qh   [TOKF];
__device__ float g_kh   [TOKF];
__device__ float g_vh   [TOKF];
__device__ float g_sain [TOKF];
__device__ float g_saout[TOKF];
__device__ float g_tgt2 [TOKF];
__device__ float g_q2   [TOKF];
__device__ float g_off  [NTOK*768];
__device__ float g_value[(long)BSZ*STOT*DIM];
__device__ float g_cain [TOKF];
__device__ float g_caout[TOKF];
__device__ float g_tgt3 [TOKF];
__device__ float g_f1   [NTOK*DFF];
__device__ float g_f2   [TOKF];
__device__ __half g_wh[W_TOTAL];   // weight fp16 plane (single term)

// ---------------- helpers ----------------
__device__ __forceinline__ uint32_t smem_u32(const void* p) {
    uint32_t a;
    asm("{ .reg .u64 t; cvta.to.shared.u64 t, %1; cvt.u32.u64 %0, t; }" : "=r"(a) : "l"(p));
    return a;
}
__device__ __forceinline__ unsigned pkh(__half a, __half b) {
    __half2 t = __halves2half2(a, b);
    return *reinterpret_cast<unsigned*>(&t);
}
__device__ __forceinline__ void mma_f16(float* d, const uint32_t* a, uint32_t b0, uint32_t b1) {
    asm volatile(
        "mma.sync.aligned.m16n8k16.row.col.f32.f16.f16.f32 "
        "{%0,%1,%2,%3}, {%4,%5,%6,%7}, {%8,%9}, {%0,%1,%2,%3};"
        : "+f"(d[0]), "+f"(d[1]), "+f"(d[2]), "+f"(d[3])
        : "r"(a[0]), "r"(a[1]), "r"(a[2]), "r"(a[3]), "r"(b0), "r"(b1));
}
__device__ __forceinline__ void ldmx4(uint32_t* r, uint32_t addr) {
    asm volatile("ldmatrix.sync.aligned.m8n8.x4.shared.b16 {%0,%1,%2,%3}, [%4];"
                 : "=r"(r[0]), "=r"(r[1]), "=r"(r[2]), "=r"(r[3]) : "r"(addr));
}
__device__ __forceinline__ uint2 cvt_a(float4 v) {
    return make_uint2(pkh(__float2half_rn(v.x), __float2half_rn(v.y)),
                      pkh(__float2half_rn(v.z), __float2half_rn(v.w)));
}

// ============ fp16 1-term GEMM: C = A(MxK fp32->fp16) * W(NxK fp16)^T + bias ============
// CTA 64x128, 256 thr, 8 warps of 32x32. K chunks 32, 2-stage ping-pong.
// Stage 12288 B: A[64x32] @0 (4KB), B[128x32] @4096 (8KB).
// Rows 64B; 16B chunks swizzled c' = c ^ ((row>>1)&3).
// EPI: 0 plain, 1 relu, 2 head-permute (C2 for n>=256), 3 pad-mask zero (batched).
#define STG 12288

template<int EPI>
__global__ void __launch_bounds__(256, 2) mma_gemm(
    const float* __restrict__ A, int lda, long aOff,
    const __half* __restrict__ B, int ldw,
    const float* __restrict__ bias,
    const __half* W2, const float* bias2, int Nsplit,
    float* __restrict__ C, float* __restrict__ C2, int ldc, long cOff,
    int M, int K,
    const unsigned char* __restrict__ mask, long mOff)
{
    extern __shared__ __align__(128) unsigned char sm[];
    const uint32_t sb = smem_u32(sm);
    const int tid = threadIdx.x;
    const int bm = blockIdx.y * 64;
    const int bn = blockIdx.x * 128;
    A += (long)blockIdx.z * aOff;
    C += (long)blockIdx.z * cOff;
    if (Nsplit && bn >= Nsplit) {
        B = W2 - (long)Nsplit * ldw;
        bias = bias2 - Nsplit;
    }

    const int warp = tid >> 5, lane = tid & 31;
    const int wm = warp & 1, wn = warp >> 1;

    // A prefetch: 64 rows x 32 k fp32 = 512 float4 (2/thr)
    int arow[2], akq[2]; bool agd[2]; const float* aptr[2]; uint32_t asw[2];
#pragma unroll
    for (int j = 0; j < 2; j++) {
        int i = tid + j * 256;
        arow[j] = i >> 3; akq[j] = i & 7;
        agd[j] = (bm + arow[j]) < M;
        aptr[j] = A + (long)(bm + arow[j]) * lda + akq[j] * 4;
        asw[j] = (uint32_t)(arow[j] * 64 + (((akq[j] >> 1) ^ ((arow[j] >> 1) & 3)) << 4) + (akq[j] & 1) * 8);
    }
    // B plane: 128 rows x 32 halves = 512 uint4 (2/thr)
    int brow[2], bch[2]; const __half* bp[2]; uint32_t bsw[2];
#pragma unroll
    for (int j = 0; j < 2; j++) {
        int i = tid + j * 256;
        brow[j] = i >> 2; bch[j] = i & 3;
        bp[j] = B + (long)(bn + brow[j]) * ldw + bch[j] * 8;
        bsw[j] = (uint32_t)(brow[j] * 64 + ((bch[j] ^ ((brow[j] >> 1) & 3)) << 4));
    }

    float acc[2][4][4];
#pragma unroll
    for (int mt = 0; mt < 2; mt++)
#pragma unroll
        for (int nt = 0; nt < 4; nt++)
#pragma unroll
            for (int r = 0; r < 4; r++) acc[mt][nt][r] = 0.f;

    const int nk = K >> 5;
    float4 av[2];
    uint4 bv[2];

    // load + stage chunk 0
#pragma unroll
    for (int j = 0; j < 2; j++) {
        av[j] = agd[j] ? *(const float4*)(aptr[j]) : make_float4(0.f,0.f,0.f,0.f);
        bv[j] = *(const uint4*)(bp[j]);
    }
#pragma unroll
    for (int j = 0; j < 2; j++) {
        *(uint2*)(sm + asw[j]) = cvt_a(av[j]);
        *(uint4*)(sm + 4096 + bsw[j]) = bv[j];
    }
    __syncthreads();

    for (int kc = 0; kc < nk; kc++) {
        const int st = kc & 1;
        const uint32_t so = sb + (uint32_t)(st * STG);
        const bool more = (kc + 1) < nk;

        if (more) {
            int kb = (kc + 1) * 32;
#pragma unroll
            for (int j = 0; j < 2; j++) {
                av[j] = agd[j] ? *(const float4*)(aptr[j] + kb) : make_float4(0.f,0.f,0.f,0.f);
                bv[j] = *(const uint4*)(bp[j] + kb);
            }
        }

#pragma unroll
        for (int ks = 0; ks < 2; ks++) {
            uint32_t af[2][4];
#pragma unroll
            for (int mt = 0; mt < 2; mt++) {
                int row = wm * 32 + mt * 16 + (lane & 7) + ((lane >> 3) & 1) * 8;
                int c = 2 * ks + (lane >> 4);
                uint32_t off = (uint32_t)(row * 64 + ((c ^ ((row >> 1) & 3)) << 4));
                ldmx4(af[mt], so + off);
            }
            uint32_t bf[4][2];
#pragma unroll
            for (int np = 0; np < 2; np++) {
                int row = wn * 32 + np * 16 + (lane & 7) + (lane >> 4) * 8;
                int c = 2 * ks + ((lane >> 3) & 1);
                uint32_t off = (uint32_t)(row * 64 + ((c ^ ((row >> 1) & 3)) << 4));
                uint32_t t[4];
                ldmx4(t, so + 4096 + off);
                bf[2*np][0] = t[0]; bf[2*np][1] = t[1];
                bf[2*np+1][0] = t[2]; bf[2*np+1][1] = t[3];
            }
#pragma unroll
            for (int mt = 0; mt < 2; mt++)
#pragma unroll
                for (int nt = 0; nt < 4; nt++)
                    mma_f16(acc[mt][nt], af[mt], bf[nt][0], bf[nt][1]);
        }

        if (more) {
            const uint32_t po = (uint32_t)((st ^ 1) * STG);
#pragma unroll
            for (int j = 0; j < 2; j++) {
                *(uint2*)(sm + po + asw[j]) = cvt_a(av[j]);
                *(uint4*)(sm + po + 4096 + bsw[j]) = bv[j];
            }
        }
        __syncthreads();
    }

    // ---------------- epilogue ----------------
#pragma unroll
    for (int mt = 0; mt < 2; mt++) {
        int r0 = bm + wm * 32 + mt * 16 + (lane >> 2);
#pragma unroll
        for (int nt = 0; nt < 4; nt++) {
            int n0 = bn + wn * 32 + nt * 8 + (lane & 3) * 2;
            float b0 = bias[n0], b1 = bias[n0 + 1];
#pragma unroll
            for (int half = 0; half < 2; half++) {
                int r = r0 + half * 8;
                if (r >= M) continue;
                float v0 = acc[mt][nt][half * 2 + 0] + b0;
                float v1 = acc[mt][nt][half * 2 + 1] + b1;
                if (EPI == 1) { v0 = fmaxf(v0, 0.f); v1 = fmaxf(v1, 0.f); }
                if (EPI == 3) {
                    if (mask[(long)blockIdx.z * mOff + r]) { v0 = 0.f; v1 = 0.f; }
                }
                if (EPI == 2) {
                    float* base = C; int nn = n0;
                    if (C2 && nn >= 256) { base = C2; nn -= 256; }
                    int q = r >> 3, bb = r & 7, hh = nn >> 5, d = nn & 31;
                    float* p = base + (((long)(bb * NH + hh)) * NQ + q) * DH + d;
                    p[0] = v0; p[1] = v1;
                } else {
                    float* p = C + (long)r * ldc + n0;
                    p[0] = v0; p[1] = v1;
                }
            }
        }
    }
}

static inline void launch_mma(int epi,
    const float* A, int lda, long aOff,
    const __half* B, int ldw, const float* bias,
    const __half* W2, const float* bias2, int Nsplit,
    float* C, float* C2, int ldc, long cOff,
    int M, int N, int K, int nz,
    const unsigned char* mask, long mOff)
{
    dim3 grid(N / 128, (M + 63) / 64, nz);
    const int SMEM = 2 * STG;
#define LM(E) do { \
    cudaFuncSetAttribute(mma_gemm<E>, cudaFuncAttributeMaxDynamicSharedMemorySize, SMEM); \
    mma_gemm<E><<<grid,256,SMEM>>>(A,lda,aOff,B,ldw,bias,W2,bias2,Nsplit, \
                                   C,C2,ldc,cOff,M,K,mask,mOff); } while (0)
    switch (epi) {
        case 0: LM(0); break;
        case 1: LM(1); break;
        case 2: LM(2); break;
        case 3: LM(3); break;
    }
#undef LM
}

// ---------------- weight convert: fp32 -> fp16 plane ----------------
struct WDesc { const float* src[8]; long off[8]; int n4[8]; };
__global__ void cvt_w_kernel(WDesc d, __half* __restrict__ hi)
{
    int w = blockIdx.y;
    int i = blockIdx.x * blockDim.x + threadIdx.x;
    if (i >= d.n4[w]) return;
    float4 v = ((const float4*)d.src[w])[i];
    ((uint2*)(hi + d.off[w]))[i] = make_uint2(
        pkh(__float2half_rn(v.x), __float2half_rn(v.y)),
        pkh(__float2half_rn(v.z), __float2half_rn(v.w)));
}

// ---------------- elementwise ----------------
__global__ void add_kernel(const float* __restrict__ a, const float* __restrict__ b,
                           float* __restrict__ o, int n4)
{
    int i = blockIdx.x * blockDim.x + threadIdx.x;
    if (i < n4) {
        float4 x = ((const float4*)a)[i], y = ((const float4*)b)[i];
        ((float4*)o)[i] = make_float4(x.x+y.x, x.y+y.y, x.z+y.z, x.w+y.w);
    }
}

__global__ void permadd_kernel(const float* __restrict__ t2, const float* __restrict__ msk,
                               float* __restrict__ q2)
{
    int i = blockIdx.x * 256 + threadIdx.x;   // over TOKF/4 float4s
    if (i >= TOKF/4) return;
    int d4 = i & 63;
    int t = i >> 6;
    int q = t >> 3, b = t & 7;
    float4 x = ((const float4*)t2)[i], y = ((const float4*)msk)[i];
    ((float4*)q2)[((long)(b*NQ + q) << 6) + d4] = make_float4(x.x+y.x, x.y+y.y, x.z+y.z, x.w+y.w);
}

// ---------------- residual + layernorm ----------------
__global__ void __launch_bounds__(256) ln_kernel(
    const float* __restrict__ A, const float* __restrict__ B, int bBQ,
    const float* __restrict__ g, const float* __restrict__ be,
    float* __restrict__ out)
{
    int t = blockIdx.x * 8 + (threadIdx.x >> 5);
    int lane = threadIdx.x & 31;
    if (t >= NTOK) return;
    const float* ap = A + (long)t * DIM + lane*8;
    long bo;
    if (bBQ) { int q = t >> 3, b = t & 7; bo = (long)(b*NQ + q) * DIM; }
    else     { bo = (long)t * DIM; }
    const float* bp = B + bo + lane*8;

    float4 x0 = *(const float4*)ap,      x1 = *(const float4*)(ap + 4);
    float4 y0 = *(const float4*)bp,      y1 = *(const float4*)(bp + 4);
    float v[8] = {x0.x+y0.x, x0.y+y0.y, x0.z+y0.z, x0.w+y0.w,
                  x1.x+y1.x, x1.y+y1.y, x1.z+y1.z, x1.w+y1.w};
    float s = 0.f;
#pragma unroll
    for (int i = 0; i < 8; i++) s += v[i];
#pragma unroll
    for (int o = 16; o; o >>= 1) s += __shfl_xor_sync(0xffffffffu, s, o);
    float mu = s * (1.f/256.f);
    float s2 = 0.f;
#pragma unroll
    for (int i = 0; i < 8; i++) { float d = v[i] - mu; s2 += d*d; }
#pragma unroll
    for (int o = 16; o; o >>= 1) s2 += __shfl_xor_sync(0xffffffffu, s2, o);
    float inv = rsqrtf(s2 * (1.f/256.f) + 1e-5f);
    int c0 = lane*8;
    float* op = out + (long)t * DIM + c0;
#pragma unroll
    for (int i = 0; i < 8; i++)
        op[i] = (v[i] - mu) * inv * g[c0+i] + be[c0+i];
}

// ---------------- fused self-attention ----------------
__global__ void __launch_bounds__(256) attn_kernel(
    const float* __restrict__ qh, const float* __restrict__ kh,
    const float* __restrict__ vh, float* __restrict__ sa_in)
{
    extern __shared__ float smf[];
    const int bh   = blockIdx.x >> 1;
    const int half = blockIdx.x & 1;
    const int b = bh >> 3, h = bh & 7;
    float* Ks = smf;
    float* Vs = Ks + 300*36;
    float* Qs = Vs + 300*36;
    float* Ps = Qs + 150*32;

    const float scale = 0.17677669529663687f;
    const float* Kg = kh + (long)bh * NQ * DH;
    const float* Vg = vh + (long)bh * NQ * DH;
    const float* Qg = qh + (long)bh * NQ * DH + (long)half * 150 * DH;
    const int tid = threadIdx.x;

    for (int i = tid; i < 2400; i += 256) {
        int r = i >> 3, c4 = (i & 7) << 2;
        float4 kv = *(const float4*)(Kg + r*32 + c4);
        float4 vv = *(const float4*)(Vg + r*32 + c4);
        *(float4*)(Ks + r*36 + c4) = kv;
        *(float4*)(Vs + r*36 + c4) = vv;
    }
    for (int i = tid; i < 1200; i += 256) {
        int r = i >> 3, c4 = (i & 7) << 2;
        float4 qv = *(const float4*)(Qg + r*32 + c4);
        qv.x *= scale; qv.y *= scale; qv.z *= scale; qv.w *= scale;
        *(float4*)(Qs + r*32 + c4) = qv;
    }
    __syncthreads();

    const int warp = tid >> 5, lane = tid & 31;
    float* Pw = Ps + warp * 320;

    for (int q = warp; q < 150; q += 8) {
        float4 qr[8];
#pragma unroll
        for (int d4 = 0; d4 < 8; d4++) qr[d4] = *(const float4*)(Qs + q*32 + d4*4);

        float sc[10];
#pragma unroll
        for (int j = 0; j < 10; j++) {
            int k = j*32 + lane;
            float s = -1e30f;
            if (k < 300) {
                s = 0.f;
#pragma unroll
                for (int d4 = 0; d4 < 8; d4++) {
                    float4 kv = *(const float4*)(Ks + k*36 + d4*4);
                    s = fmaf(qr[d4].x, kv.x, s);
                    s = fmaf(qr[d4].y, kv.y, s);
                    s = fmaf(qr[d4].z, kv.z, s);
                    s = fmaf(qr[d4].w, kv.w, s);
                }
            }
            sc[j] = s;
        }
        float m = sc[0];
#pragma unroll
        for (int j = 1; j < 10; j++) m = fmaxf(m, sc[j]);
#pragma unroll
        for (int o = 16; o; o >>= 1) m = fmaxf(m, __shfl_xor_sync(0xffffffffu, m, o));
        float sum = 0.f;
#pragma unroll
        for (int j = 0; j < 10; j++) { sc[j] = expf(sc[j] - m); sum += sc[j]; }
#pragma unroll
        for (int o = 16; o; o >>= 1) sum += __shfl_xor_sync(0xffffffffu, sum, o);
        float inv = 1.f / sum;
#pragma unroll
        for (int j = 0; j < 10; j++) Pw[j*32 + lane] = sc[j] * inv;
        __syncwarp();

        float acc = 0.f;
#pragma unroll 4
        for (int k = 0; k < 300; k++)
            acc = fmaf(Pw[k], Vs[k*36 + lane], acc);

        int qg = half*150 + q;
        sa_in[((long)(qg*BSZ + b)) * DIM + h*DH + lane] = acc;
        __syncwarp();
    }
}

// ---------------- multi-scale deformable sampling ----------------
__global__ void __launch_bounds__(256) deform_kernel(
    const float* __restrict__ offaw,
    const float* __restrict__ bbox, const float* __restrict__ value,
    const int* __restrict__ spatial, const int* __restrict__ lstart,
    float* __restrict__ ca_in)
{
    __shared__ float s_w[8][32][4];
    __shared__ int   s_i[8][32][4];
    int bq = blockIdx.x;
    int b = bq / NQ, q = bq - b*NQ;
    int warp = threadIdx.x >> 5, lane = threadIdx.x & 31;

    const float* tok = offaw + (long)bq * 768;
    float a = tok[512 + warp*32 + lane];
    float m = a;
#pragma unroll
    for (int o = 16; o; o >>= 1) m = fmaxf(m, __shfl_xor_sync(0xffffffffu, m, o));
    float e = expf(a - m);
    float s = e;
#pragma unroll
    for (int o = 16; o; o >>= 1) s += __shfl_xor_sync(0xffffffffu, s, o);
    float p = e / s;

    float ox = tok[warp*64 + lane*2];
    float oy = tok[warp*64 + lane*2 + 1];
    const float* rb = bbox + ((long)q*BSZ + b)*4;
    float r0 = rb[0], r1 = rb[1], r2 = rb[2], r3 = rb[3];

    int lvl = lane >> 3;
    int H = spatial[lvl*2], W = spatial[lvl*2 + 1], ls = lstart[lvl];
    float Wf = (float)W, Hf = (float)H;
    float x = (r0 + ox*0.0625f*r2) * Wf - 0.5f;
    float y = (r1 + oy*0.0625f*r3) * Hf - 0.5f;
    float x0 = floorf(x), y0 = floorf(y);
    float fx = x - x0, fy = y - y0;

#pragma unroll
    for (int c = 0; c < 4; c++) {
        float xi = x0 + (float)(c & 1);
        float yi = y0 + (float)(c >> 1);
        float wgt = ((c & 1) ? fx : 1.f - fx) * ((c >> 1) ? fy : 1.f - fy);
        bool valid = (xi >= 0.f) && (xi < Wf) && (yi >= 0.f) && (yi < Hf);
        int xc = (int)fminf(fmaxf(xi, 0.f), Wf - 1.f);
        int yc = (int)fminf(fmaxf(yi, 0.f), Hf - 1.f);
        s_i[warp][lane][c] = ls + yc*W + xc;
        s_w[warp][lane][c] = valid ? wgt * p : 0.f;
    }
    __syncwarp();

    const float* vb = value + (long)b * STOT * DIM + warp*DH + lane;
    float acc = 0.f;
    for (int lp = 0; lp < 32; lp++) {
#pragma unroll
        for (int c = 0; c < 4; c++) {
            float wgt = s_w[warp][lp][c];
            if (wgt != 0.f)
                acc = fmaf(wgt, vb[(long)s_i[warp][lp][c] << 8], acc);
        }
    }
    ca_in[(long)bq*DIM + warp*DH + lane] = acc;
}

// ---------------- host orchestration (single stream; no allocations) ----------------
extern "C" void kernel_launch(void* const* d_in, const int* in_sizes, int n_in,
                              void* d_out, int out_size)
{
    const float* tgt        = (const float*)d_in[0];
    const float* qmask      = (const float*)d_in[1];
    const float* bbox       = (const float*)d_in[2];
    const float* memory     = (const float*)d_in[4];
    const float* in_proj_w  = (const float*)d_in[5];
    const float* in_proj_b  = (const float*)d_in[6];
    const float* out_sa_w   = (const float*)d_in[7];
    const float* out_sa_b   = (const float*)d_in[8];
    const float* norm2_g    = (const float*)d_in[9];
    const float* norm2_b    = (const float*)d_in[10];
    const float* value_w    = (const float*)d_in[11];
    const float* value_b    = (const float*)d_in[12];
    const float* off_w      = (const float*)d_in[13];
    const float* off_b      = (const float*)d_in[14];
    const float* aw_w       = (const float*)d_in[15];
    const float* aw_b       = (const float*)d_in[16];
    const float* out_ca_w   = (const float*)d_in[17];
    const float* out_ca_b   = (const float*)d_in[18];
    const float* norm1_g    = (const float*)d_in[19];
    const float* norm1_b    = (const float*)d_in[20];
    const float* lin1_w     = (const float*)d_in[21];
    const float* lin1_b     = (const float*)d_in[22];
    const float* lin2_w     = (const float*)d_in[23];
    const float* lin2_b     = (const float*)d_in[24];
    const float* norm3_g    = (const float*)d_in[25];
    const float* norm3_b    = (const float*)d_in[26];
    const unsigned char* pmask = (const unsigned char*)d_in[27];
    const int* spatial      = (const int*)d_in[28];
    const int* lstart       = (const int*)d_in[29];
    float* out = (float*)d_out;

    float *qbuf,*qh,*kh,*vh,*sain,*saout,*tgt2,*q2,*offb,*val,*cain,*caout,*tgt3,*f1,*f2;
    __half *wh;
    cudaGetSymbolAddress((void**)&qbuf,  g_qbuf);
    cudaGetSymbolAddress((void**)&qh,    g_qh);
    cudaGetSymbolAddress((void**)&kh,    g_kh);
    cudaGetSymbolAddress((void**)&vh,    g_vh);
    cudaGetSymbolAddress((void**)&sain,  g_sain);
    cudaGetSymbolAddress((void**)&saout, g_saout);
    cudaGetSymbolAddress((void**)&tgt2,  g_tgt2);
    cudaGetSymbolAddress((void**)&q2,    g_q2);
    cudaGetSymbolAddress((void**)&offb,  g_off);
    cudaGetSymbolAddress((void**)&val,   g_value);
    cudaGetSymbolAddress((void**)&cain,  g_cain);
    cudaGetSymbolAddress((void**)&caout, g_caout);
    cudaGetSymbolAddress((void**)&tgt3,  g_tgt3);
    cudaGetSymbolAddress((void**)&f1,    g_f1);
    cudaGetSymbolAddress((void**)&f2,    g_f2);
    cudaGetSymbolAddress((void**)&wh,    g_wh);

    // 0) weight plane (fp16) — one cheap kernel
    {
        WDesc d;
        d.src[0]=in_proj_w; d.off[0]=W_INPROJ; d.n4[0]=196608/4;
        d.src[1]=out_sa_w;  d.off[1]=W_OUTSA;  d.n4[1]=65536/4;
        d.src[2]=value_w;   d.off[2]=W_VALUE;  d.n4[2]=65536/4;
        d.src[3]=off_w;     d.off[3]=W_OFF;    d.n4[3]=131072/4;
        d.src[4]=aw_w;      d.off[4]=W_AW;     d.n4[4]=65536/4;
        d.src[5]=out_ca_w;  d.off[5]=W_OUTCA;  d.n4[5]=65536/4;
        d.src[6]=lin1_w;    d.off[6]=W_LIN1;   d.n4[6]=262144/4;
        d.src[7]=lin2_w;    d.off[7]=W_LIN2;   d.n4[7]=262144/4;
        dim3 g((262144/4 + 255)/256, 8);
        cvt_w_kernel<<<g, 256>>>(d, wh);
    }

    // 1) q = tgt + query_mask
    add_kernel<<<TOKF/4/256, 256>>>(tgt, qmask, qbuf, TOKF/4);

    // 2) value projection over memory (batched over BS), pad-mask epilogue
    launch_mma(3, memory, BSZ*DIM, 256, wh+W_VALUE, DIM, value_b,
               nullptr, nullptr, 0,
               val, nullptr, DIM, (long)STOT*DIM,
               STOT, DIM, DIM, BSZ, pmask, STOT);

    // 3) Q+K merged (N=512), then V
    launch_mma(2, qbuf, DIM, 0, wh+W_INPROJ, DIM, in_proj_b,
               nullptr, nullptr, 0,
               qh, kh, 0, 0, NTOK, 512, DIM, 1, nullptr, 0);
    launch_mma(2, tgt, DIM, 0, wh+W_INPROJ+512*256, DIM, in_proj_b+512,
               nullptr, nullptr, 0,
               vh, nullptr, 0, 0, NTOK, 256, DIM, 1, nullptr, 0);

    // 4) fused self-attention
    {
        int smem = (300*36*2 + 150*32 + 8*320) * 4;
        cudaFuncSetAttribute(attn_kernel, cudaFuncAttributeMaxDynamicSharedMemorySize, smem);
        attn_kernel<<<128, 256, smem>>>(qh, kh, vh, sain);
    }

    // 5) self-attn out-proj + residual LN (norm2)
    launch_mma(0, sain, DIM, 0, wh+W_OUTSA, DIM, out_sa_b,
               nullptr, nullptr, 0,
               saout, nullptr, DIM, 0, NTOK, DIM, DIM, 1, nullptr, 0);
    ln_kernel<<<NTOK/8, 256>>>(tgt, saout, 0, norm2_g, norm2_b, tgt2);

    // 6) query2 = (tgt2 + mask) in (b,q,d) layout
    permadd_kernel<<<(TOKF/4 + 255)/256, 256>>>(tgt2, qmask, q2);

    // 7) offsets + aw logits merged (N=768, split at 512)
    launch_mma(0, q2, DIM, 0, wh+W_OFF, DIM, off_b,
               wh+W_AW, aw_b, 512,
               offb, nullptr, 768, 0, NTOK, 768, DIM, 1, nullptr, 0);

    // 8) deformable sampling
    deform_kernel<<<NTOK, 256>>>(offb, bbox, val, spatial, lstart, cain);

    // 9) cross-attn out-proj + residual LN (norm1)
    launch_mma(0, cain, DIM, 0, wh+W_OUTCA, DIM, out_ca_b,
               nullptr, nullptr, 0,
               caout, nullptr, DIM, 0, NTOK, DIM, DIM, 1, nullptr, 0);
    ln_kernel<<<NTOK/8, 256>>>(tgt2, caout, 1, norm1_g, norm1_b, tgt3);

    // 10) FFN + final LN (norm3) -> d_out
    launch_mma(1, tgt3, DIM, 0, wh+W_LIN1, DIM, lin1_b,
               nullptr, nullptr, 0,
               f1, nullptr, DFF, 0, NTOK, DFF, DIM, 1, nullptr, 0);
    launch_mma(0, f1, DFF, 0, wh+W_LIN2, DFF, lin2_b,
               nullptr, nullptr, 0,
               f2, nullptr, DIM, 0, NTOK, DIM, DFF, 1, nullptr, 0);
    ln_kernel<<<NTOK/8, 256>>>(tgt3, f2, 0, norm3_g, norm3_b, out);
}

// round 15
// speedup vs baseline: 1.5901x; 1.1493x over previous
#include <cuda_runtime.h>
#include <cuda_fp16.h>
#include <math.h>
#include <cstdint>

// ---------------- problem constants ----------------
#define NQ   300
#define BSZ  8
#define DIM  256
#define NH   8
#define DH   32
#define DFF  1024
#define STOT 13294
#define NTOK (NQ*BSZ)          // 2400
#define TOKF (NTOK*DIM)        // 614400

// weight plane offsets (elements)
#define W_INPROJ 0L
#define W_OUTSA  196608L
#define W_VALUE  262144L
#define W_OFF    327680L
#define W_AW     458752L
#define W_OUTCA  524288L
#define W_LIN1   589824L
#define W_LIN2   851968L
#define W_TOTAL  1114112L

// ---------------- scratch (static device globals; no allocations) ----------------
__device__ float g_qbuf [TOKF];
__device__ float g_qh   [TOKF];
__device__ float g_kh   [TOKF];
__device__ float g_vh   [TOKF];
__device__ float g_sain [TOKF];
__device__ float g_saout[TOKF];
__device__ float g_tgt2 [TOKF];
__device__ float g_q2   [TOKF];
__device__ float g_off  [NTOK*768];
__device__ float g_value[(long)BSZ*STOT*DIM];
__device__ float g_cain [TOKF];
__device__ float g_caout[TOKF];
__device__ float g_tgt3 [TOKF];
__device__ float g_f1   [NTOK*DFF];
__device__ float g_f2   [TOKF];
__device__ __half g_wh[W_TOTAL];   // weight fp16 plane

// ---------------- helpers ----------------
__device__ __forceinline__ uint32_t smem_u32(const void* p) {
    uint32_t a;
    asm("{ .reg .u64 t; cvta.to.shared.u64 t, %1; cvt.u32.u64 %0, t; }" : "=r"(a) : "l"(p));
    return a;
}
__device__ __forceinline__ unsigned pkh(__half a, __half b) {
    __half2 t = __halves2half2(a, b);
    return *reinterpret_cast<unsigned*>(&t);
}
__device__ __forceinline__ void mma_f16(float* d, const uint32_t* a, uint32_t b0, uint32_t b1) {
    asm volatile(
        "mma.sync.aligned.m16n8k16.row.col.f32.f16.f16.f32 "
        "{%0,%1,%2,%3}, {%4,%5,%6,%7}, {%8,%9}, {%0,%1,%2,%3};"
        : "+f"(d[0]), "+f"(d[1]), "+f"(d[2]), "+f"(d[3])
        : "r"(a[0]), "r"(a[1]), "r"(a[2]), "r"(a[3]), "r"(b0), "r"(b1));
}
__device__ __forceinline__ void ldmx4(uint32_t* r, uint32_t addr) {
    asm volatile("ldmatrix.sync.aligned.m8n8.x4.shared.b16 {%0,%1,%2,%3}, [%4];"
                 : "=r"(r[0]), "=r"(r[1]), "=r"(r[2]), "=r"(r[3]) : "r"(addr));
}
__device__ __forceinline__ uint2 cvt_a(float4 v) {
    return make_uint2(pkh(__float2half_rn(v.x), __float2half_rn(v.y)),
                      pkh(__float2half_rn(v.z), __float2half_rn(v.w)));
}
#define CP16(dst, src) \
    asm volatile("cp.async.cg.shared.global [%0], [%1], 16;" \
                 :: "r"(dst), "l"(src) : "memory")
#define CP_COMMIT() asm volatile("cp.async.commit_group;" ::: "memory")
#define CP_WAIT1()  asm volatile("cp.async.wait_group 1;" ::: "memory")

// ============ fp16 1-term GEMM, K-chunk 64: C = A(fp32->fp16) * W(fp16)^T + bias ============
// CTA 64x128, 256 thr, 8 warps of 32x32.
// A: register convert, 2-stage ping-pong (8KB/stage @0, @8192).
// B: cp.async 3-stage (16KB/stage @16384 + st*16384). Total smem 65536.
// Chunk = 64 k, stored as two 32-k sub-blocks (4KB A / 8KB B each), rows 64B,
// 16B chunks swizzled c' = c ^ ((row>>1)&3).
// EPI: 0 plain, 1 relu, 2 head-permute (C2 for n>=256), 3 pad-mask zero (batched).
template<int EPI>
__global__ void __launch_bounds__(256, 2) mma_gemm(
    const float* __restrict__ A, int lda, long aOff,
    const __half* __restrict__ B, int ldw,
    const float* __restrict__ bias,
    const __half* W2, const float* bias2, int Nsplit,
    float* __restrict__ C, float* __restrict__ C2, int ldc, long cOff,
    int M, int K,
    const unsigned char* __restrict__ mask, long mOff)
{
    extern __shared__ __align__(128) unsigned char sm[];
    const uint32_t sb = smem_u32(sm);
    const int tid = threadIdx.x;
    const int bm = blockIdx.y * 64;
    const int bn = blockIdx.x * 128;
    A += (long)blockIdx.z * aOff;
    C += (long)blockIdx.z * cOff;
    if (Nsplit && bn >= Nsplit) {
        B = W2 - (long)Nsplit * ldw;
        bias = bias2 - Nsplit;
    }

    const int warp = tid >> 5, lane = tid & 31;
    const int wm = warp & 1, wn = warp >> 1;

    // A: 64 rows x 64 k fp32 = 1024 float4 (4/thr)
    int arow[4]; bool agd[4]; const float* aptr[4]; uint32_t asw[4];
#pragma unroll
    for (int j = 0; j < 4; j++) {
        int i = tid + j * 256;
        int row = i >> 4, kq = i & 15;
        int sub = kq >> 3, kq2 = kq & 7;
        arow[j] = row;
        agd[j] = (bm + row) < M;
        aptr[j] = A + (long)(bm + row) * lda + kq * 4;
        asw[j] = (uint32_t)(sub * 4096 + row * 64 + (((kq2 >> 1) ^ ((row >> 1) & 3)) << 4) + (kq2 & 1) * 8);
    }
    // B: 128 rows x 64 halves = 1024 x 16B (4/thr), cp.async
    const __half* bp[4]; uint32_t bsw[4];
#pragma unroll
    for (int j = 0; j < 4; j++) {
        int i = tid + j * 256;
        int row = i >> 3, c8 = i & 7;
        int sub = c8 >> 2, c = c8 & 3;
        bp[j] = B + (long)(bn + row) * ldw + sub * 32 + c * 8;
        bsw[j] = (uint32_t)(sub * 8192 + row * 64 + ((c ^ ((row >> 1) & 3)) << 4));
    }

    float acc[2][4][4];
#pragma unroll
    for (int mt = 0; mt < 2; mt++)
#pragma unroll
        for (int nt = 0; nt < 4; nt++)
#pragma unroll
            for (int r = 0; r < 4; r++) acc[mt][nt][r] = 0.f;

    const int nk = K >> 6;   // chunks of 64

#define ISSUE_B(kc, st) do { \
    if ((kc) < nk) { \
        const int kb = (kc) * 64; \
        const uint32_t so = sb + 16384u + (uint32_t)((st) * 16384); \
        CP16(so + bsw[0], bp[0] + kb); \
        CP16(so + bsw[1], bp[1] + kb); \
        CP16(so + bsw[2], bp[2] + kb); \
        CP16(so + bsw[3], bp[3] + kb); \
    } \
    CP_COMMIT(); \
} while (0)

    float4 av[4];

    // prologue: B chunks 0,1 async; A chunk 0 staged; A chunk 1 in regs
    ISSUE_B(0, 0);
    ISSUE_B(1, 1);
#pragma unroll
    for (int j = 0; j < 4; j++)
        av[j] = agd[j] ? *(const float4*)(aptr[j]) : make_float4(0.f,0.f,0.f,0.f);
#pragma unroll
    for (int j = 0; j < 4; j++)
        *(uint2*)(sm + asw[j]) = cvt_a(av[j]);
    if (nk > 1) {
#pragma unroll
        for (int j = 0; j < 4; j++)
            av[j] = agd[j] ? *(const float4*)(aptr[j] + 64) : make_float4(0.f,0.f,0.f,0.f);
    }
    CP_WAIT1();
    __syncthreads();

    for (int kc = 0; kc < nk; kc++) {
        ISSUE_B(kc + 2, (kc + 2) % 3);

        const uint32_t soa = sb + (uint32_t)((kc & 1) * 8192);
        const uint32_t sob = sb + 16384u + (uint32_t)((kc % 3) * 16384);

        // compute: 4 k16 steps
#pragma unroll
        for (int ks = 0; ks < 4; ks++) {
            const uint32_t suba = soa + (uint32_t)((ks >> 1) * 4096);
            const uint32_t subb = sob + (uint32_t)((ks >> 1) * 8192);
            const int kk = ks & 1;
            uint32_t af[2][4];
#pragma unroll
            for (int mt = 0; mt < 2; mt++) {
                int row = wm * 32 + mt * 16 + (lane & 7) + ((lane >> 3) & 1) * 8;
                int c = 2 * kk + (lane >> 4);
                uint32_t off = (uint32_t)(row * 64 + ((c ^ ((row >> 1) & 3)) << 4));
                ldmx4(af[mt], suba + off);
            }
            uint32_t bf[4][2];
#pragma unroll
            for (int np = 0; np < 2; np++) {
                int row = wn * 32 + np * 16 + (lane & 7) + (lane >> 4) * 8;
                int c = 2 * kk + ((lane >> 3) & 1);
                uint32_t off = (uint32_t)(row * 64 + ((c ^ ((row >> 1) & 3)) << 4));
                uint32_t t[4];
                ldmx4(t, subb + off);
                bf[2*np][0] = t[0]; bf[2*np][1] = t[1];
                bf[2*np+1][0] = t[2]; bf[2*np+1][1] = t[3];
            }
#pragma unroll
            for (int mt = 0; mt < 2; mt++)
#pragma unroll
                for (int nt = 0; nt < 4; nt++)
                    mma_f16(acc[mt][nt], af[mt], bf[nt][0], bf[nt][1]);
        }

        // stage A for chunk kc+1 into the other stage; preload A regs for kc+2
        if (kc + 1 < nk) {
            const uint32_t po = sb + (uint32_t)(((kc + 1) & 1) * 8192);
#pragma unroll
            for (int j = 0; j < 4; j++)
                *(uint2*)(sm + (po - sb) + asw[j]) = cvt_a(av[j]);
            if (kc + 2 < nk) {
                int kb = (kc + 2) * 64;
#pragma unroll
                for (int j = 0; j < 4; j++)
                    av[j] = agd[j] ? *(const float4*)(aptr[j] + kb) : make_float4(0.f,0.f,0.f,0.f);
            }
        }
        CP_WAIT1();
        __syncthreads();
    }
#undef ISSUE_B

    // ---------------- epilogue ----------------
#pragma unroll
    for (int mt = 0; mt < 2; mt++) {
        int r0 = bm + wm * 32 + mt * 16 + (lane >> 2);
#pragma unroll
        for (int nt = 0; nt < 4; nt++) {
            int n0 = bn + wn * 32 + nt * 8 + (lane & 3) * 2;
            float b0 = bias[n0], b1 = bias[n0 + 1];
#pragma unroll
            for (int half = 0; half < 2; half++) {
                int r = r0 + half * 8;
                if (r >= M) continue;
                float v0 = acc[mt][nt][half * 2 + 0] + b0;
                float v1 = acc[mt][nt][half * 2 + 1] + b1;
                if (EPI == 1) { v0 = fmaxf(v0, 0.f); v1 = fmaxf(v1, 0.f); }
                if (EPI == 3) {
                    if (mask[(long)blockIdx.z * mOff + r]) { v0 = 0.f; v1 = 0.f; }
                }
                if (EPI == 2) {
                    float* base = C; int nn = n0;
                    if (C2 && nn >= 256) { base = C2; nn -= 256; }
                    int q = r >> 3, bb = r & 7, hh = nn >> 5, d = nn & 31;
                    float* p = base + (((long)(bb * NH + hh)) * NQ + q) * DH + d;
                    p[0] = v0; p[1] = v1;
                } else {
                    float* p = C + (long)r * ldc + n0;
                    p[0] = v0; p[1] = v1;
                }
            }
        }
    }
}

static inline void launch_mma(int epi,
    const float* A, int lda, long aOff,
    const __half* B, int ldw, const float* bias,
    const __half* W2, const float* bias2, int Nsplit,
    float* C, float* C2, int ldc, long cOff,
    int M, int N, int K, int nz,
    const unsigned char* mask, long mOff)
{
    dim3 grid(N / 128, (M + 63) / 64, nz);
    const int SMEM = 65536;
#define LM(E) do { \
    cudaFuncSetAttribute(mma_gemm<E>, cudaFuncAttributeMaxDynamicSharedMemorySize, SMEM); \
    mma_gemm<E><<<grid,256,SMEM>>>(A,lda,aOff,B,ldw,bias,W2,bias2,Nsplit, \
                                   C,C2,ldc,cOff,M,K,mask,mOff); } while (0)
    switch (epi) {
        case 0: LM(0); break;
        case 1: LM(1); break;
        case 2: LM(2); break;
        case 3: LM(3); break;
    }
#undef LM
}

// ---------------- weight convert: fp32 -> fp16 plane ----------------
struct WDesc { const float* src[8]; long off[8]; int n4[8]; };
__global__ void cvt_w_kernel(WDesc d, __half* __restrict__ hi)
{
    int w = blockIdx.y;
    int i = blockIdx.x * blockDim.x + threadIdx.x;
    if (i >= d.n4[w]) return;
    float4 v = ((const float4*)d.src[w])[i];
    ((uint2*)(hi + d.off[w]))[i] = make_uint2(
        pkh(__float2half_rn(v.x), __float2half_rn(v.y)),
        pkh(__float2half_rn(v.z), __float2half_rn(v.w)));
}

// ---------------- elementwise ----------------
__global__ void add_kernel(const float* __restrict__ a, const float* __restrict__ b,
                           float* __restrict__ o, int n4)
{
    int i = blockIdx.x * blockDim.x + threadIdx.x;
    if (i < n4) {
        float4 x = ((const float4*)a)[i], y = ((const float4*)b)[i];
        ((float4*)o)[i] = make_float4(x.x+y.x, x.y+y.y, x.z+y.z, x.w+y.w);
    }
}

__global__ void permadd_kernel(const float* __restrict__ t2, const float* __restrict__ msk,
                               float* __restrict__ q2)
{
    int i = blockIdx.x * 256 + threadIdx.x;   // over TOKF/4 float4s
    if (i >= TOKF/4) return;
    int d4 = i & 63;
    int t = i >> 6;
    int q = t >> 3, b = t & 7;
    float4 x = ((const float4*)t2)[i], y = ((const float4*)msk)[i];
    ((float4*)q2)[((long)(b*NQ + q) << 6) + d4] = make_float4(x.x+y.x, x.y+y.y, x.z+y.z, x.w+y.w);
}

// ---------------- residual + layernorm ----------------
__global__ void __launch_bounds__(256) ln_kernel(
    const float* __restrict__ A, const float* __restrict__ B, int bBQ,
    const float* __restrict__ g, const float* __restrict__ be,
    float* __restrict__ out)
{
    int t = blockIdx.x * 8 + (threadIdx.x >> 5);
    int lane = threadIdx.x & 31;
    if (t >= NTOK) return;
    const float* ap = A + (long)t * DIM + lane*8;
    long bo;
    if (bBQ) { int q = t >> 3, b = t & 7; bo = (long)(b*NQ + q) * DIM; }
    else     { bo = (long)t * DIM; }
    const float* bp = B + bo + lane*8;

    float4 x0 = *(const float4*)ap,      x1 = *(const float4*)(ap + 4);
    float4 y0 = *(const float4*)bp,      y1 = *(const float4*)(bp + 4);
    float v[8] = {x0.x+y0.x, x0.y+y0.y, x0.z+y0.z, x0.w+y0.w,
                  x1.x+y1.x, x1.y+y1.y, x1.z+y1.z, x1.w+y1.w};
    float s = 0.f;
#pragma unroll
    for (int i = 0; i < 8; i++) s += v[i];
#pragma unroll
    for (int o = 16; o; o >>= 1) s += __shfl_xor_sync(0xffffffffu, s, o);
    float mu = s * (1.f/256.f);
    float s2 = 0.f;
#pragma unroll
    for (int i = 0; i < 8; i++) { float d = v[i] - mu; s2 += d*d; }
#pragma unroll
    for (int o = 16; o; o >>= 1) s2 += __shfl_xor_sync(0xffffffffu, s2, o);
    float inv = rsqrtf(s2 * (1.f/256.f) + 1e-5f);
    int c0 = lane*8;
    float* op = out + (long)t * DIM + c0;
#pragma unroll
    for (int i = 0; i < 8; i++)
        op[i] = (v[i] - mu) * inv * g[c0+i] + be[c0+i];
}

// ---------------- fused self-attention ----------------
__global__ void __launch_bounds__(256) attn_kernel(
    const float* __restrict__ qh, const float* __restrict__ kh,
    const float* __restrict__ vh, float* __restrict__ sa_in)
{
    extern __shared__ float smf[];
    const int bh   = blockIdx.x >> 1;
    const int half = blockIdx.x & 1;
    const int b = bh >> 3, h = bh & 7;
    float* Ks = smf;
    float* Vs = Ks + 300*36;
    float* Qs = Vs + 300*36;
    float* Ps = Qs + 150*32;

    const float scale = 0.17677669529663687f;
    const float* Kg = kh + (long)bh * NQ * DH;
    const float* Vg = vh + (long)bh * NQ * DH;
    const float* Qg = qh + (long)bh * NQ * DH + (long)half * 150 * DH;
    const int tid = threadIdx.x;

    for (int i = tid; i < 2400; i += 256) {
        int r = i >> 3, c4 = (i & 7) << 2;
        float4 kv = *(const float4*)(Kg + r*32 + c4);
        float4 vv = *(const float4*)(Vg + r*32 + c4);
        *(float4*)(Ks + r*36 + c4) = kv;
        *(float4*)(Vs + r*36 + c4) = vv;
    }
    for (int i = tid; i < 1200; i += 256) {
        int r = i >> 3, c4 = (i & 7) << 2;
        float4 qv = *(const float4*)(Qg + r*32 + c4);
        qv.x *= scale; qv.y *= scale; qv.z *= scale; qv.w *= scale;
        *(float4*)(Qs + r*32 + c4) = qv;
    }
    __syncthreads();

    const int warp = tid >> 5, lane = tid & 31;
    float* Pw = Ps + warp * 320;

    for (int q = warp; q < 150; q += 8) {
        float4 qr[8];
#pragma unroll
        for (int d4 = 0; d4 < 8; d4++) qr[d4] = *(const float4*)(Qs + q*32 + d4*4);

        float sc[10];
#pragma unroll
        for (int j = 0; j < 10; j++) {
            int k = j*32 + lane;
            float s = -1e30f;
            if (k < 300) {
                s = 0.f;
#pragma unroll
                for (int d4 = 0; d4 < 8; d4++) {
                    float4 kv = *(const float4*)(Ks + k*36 + d4*4);
                    s = fmaf(qr[d4].x, kv.x, s);
                    s = fmaf(qr[d4].y, kv.y, s);
                    s = fmaf(qr[d4].z, kv.z, s);
                    s = fmaf(qr[d4].w, kv.w, s);
                }
            }
            sc[j] = s;
        }
        float m = sc[0];
#pragma unroll
        for (int j = 1; j < 10; j++) m = fmaxf(m, sc[j]);
#pragma unroll
        for (int o = 16; o; o >>= 1) m = fmaxf(m, __shfl_xor_sync(0xffffffffu, m, o));
        float sum = 0.f;
#pragma unroll
        for (int j = 0; j < 10; j++) { sc[j] = expf(sc[j] - m); sum += sc[j]; }
#pragma unroll
        for (int o = 16; o; o >>= 1) sum += __shfl_xor_sync(0xffffffffu, sum, o);
        float inv = 1.f / sum;
#pragma unroll
        for (int j = 0; j < 10; j++) Pw[j*32 + lane] = sc[j] * inv;
        __syncwarp();

        float acc = 0.f;
#pragma unroll 4
        for (int k = 0; k < 300; k++)
            acc = fmaf(Pw[k], Vs[k*36 + lane], acc);

        int qg = half*150 + q;
        sa_in[((long)(qg*BSZ + b)) * DIM + h*DH + lane] = acc;
        __syncwarp();
    }
}

// ---------------- multi-scale deformable sampling ----------------
__global__ void __launch_bounds__(256) deform_kernel(
    const float* __restrict__ offaw,
    const float* __restrict__ bbox, const float* __restrict__ value,
    const int* __restrict__ spatial, const int* __restrict__ lstart,
    float* __restrict__ ca_in)
{
    __shared__ float s_w[8][32][4];
    __shared__ int   s_i[8][32][4];
    int bq = blockIdx.x;
    int b = bq / NQ, q = bq - b*NQ;
    int warp = threadIdx.x >> 5, lane = threadIdx.x & 31;

    const float* tok = offaw + (long)bq * 768;
    float a = tok[512 + warp*32 + lane];
    float m = a;
#pragma unroll
    for (int o = 16; o; o >>= 1) m = fmaxf(m, __shfl_xor_sync(0xffffffffu, m, o));
    float e = expf(a - m);
    float s = e;
#pragma unroll
    for (int o = 16; o; o >>= 1) s += __shfl_xor_sync(0xffffffffu, s, o);
    float p = e / s;

    float ox = tok[warp*64 + lane*2];
    float oy = tok[warp*64 + lane*2 + 1];
    const float* rb = bbox + ((long)q*BSZ + b)*4;
    float r0 = rb[0], r1 = rb[1], r2 = rb[2], r3 = rb[3];

    int lvl = lane >> 3;
    int H = spatial[lvl*2], W = spatial[lvl*2 + 1], ls = lstart[lvl];
    float Wf = (float)W, Hf = (float)H;
    float x = (r0 + ox*0.0625f*r2) * Wf - 0.5f;
    float y = (r1 + oy*0.0625f*r3) * Hf - 0.5f;
    float x0 = floorf(x), y0 = floorf(y);
    float fx = x - x0, fy = y - y0;

#pragma unroll
    for (int c = 0; c < 4; c++) {
        float xi = x0 + (float)(c & 1);
        float yi = y0 + (float)(c >> 1);
        float wgt = ((c & 1) ? fx : 1.f - fx) * ((c >> 1) ? fy : 1.f - fy);
        bool valid = (xi >= 0.f) && (xi < Wf) && (yi >= 0.f) && (yi < Hf);
        int xc = (int)fminf(fmaxf(xi, 0.f), Wf - 1.f);
        int yc = (int)fminf(fmaxf(yi, 0.f), Hf - 1.f);
        s_i[warp][lane][c] = ls + yc*W + xc;
        s_w[warp][lane][c] = valid ? wgt * p : 0.f;
    }
    __syncwarp();

    const float* vb = value + (long)b * STOT * DIM + warp*DH + lane;
    float acc = 0.f;
    for (int lp = 0; lp < 32; lp++) {
#pragma unroll
        for (int c = 0; c < 4; c++) {
            float wgt = s_w[warp][lp][c];
            if (wgt != 0.f)
                acc = fmaf(wgt, vb[(long)s_i[warp][lp][c] << 8], acc);
        }
    }
    ca_in[(long)bq*DIM + warp*DH + lane] = acc;
}

// ---------------- host orchestration (single stream; no allocations) ----------------
extern "C" void kernel_launch(void* const* d_in, const int* in_sizes, int n_in,
                              void* d_out, int out_size)
{
    const float* tgt        = (const float*)d_in[0];
    const float* qmask      = (const float*)d_in[1];
    const float* bbox       = (const float*)d_in[2];
    const float* memory     = (const float*)d_in[4];
    const float* in_proj_w  = (const float*)d_in[5];
    const float* in_proj_b  = (const float*)d_in[6];
    const float* out_sa_w   = (const float*)d_in[7];
    const float* out_sa_b   = (const float*)d_in[8];
    const float* norm2_g    = (const float*)d_in[9];
    const float* norm2_b    = (const float*)d_in[10];
    const float* value_w    = (const float*)d_in[11];
    const float* value_b    = (const float*)d_in[12];
    const float* off_w      = (const float*)d_in[13];
    const float* off_b      = (const float*)d_in[14];
    const float* aw_w       = (const float*)d_in[15];
    const float* aw_b       = (const float*)d_in[16];
    const float* out_ca_w   = (const float*)d_in[17];
    const float* out_ca_b   = (const float*)d_in[18];
    const float* norm1_g    = (const float*)d_in[19];
    const float* norm1_b    = (const float*)d_in[20];
    const float* lin1_w     = (const float*)d_in[21];
    const float* lin1_b     = (const float*)d_in[22];
    const float* lin2_w     = (const float*)d_in[23];
    const float* lin2_b     = (const float*)d_in[24];
    const float* norm3_g    = (const float*)d_in[25];
    const float* norm3_b    = (const float*)d_in[26];
    const unsigned char* pmask = (const unsigned char*)d_in[27];
    const int* spatial      = (const int*)d_in[28];
    const int* lstart       = (const int*)d_in[29];
    float* out = (float*)d_out;

    float *qbuf,*qh,*kh,*vh,*sain,*saout,*tgt2,*q2,*offb,*val,*cain,*caout,*tgt3,*f1,*f2;
    __half *wh;
    cudaGetSymbolAddress((void**)&qbuf,  g_qbuf);
    cudaGetSymbolAddress((void**)&qh,    g_qh);
    cudaGetSymbolAddress((void**)&kh,    g_kh);
    cudaGetSymbolAddress((void**)&vh,    g_vh);
    cudaGetSymbolAddress((void**)&sain,  g_sain);
    cudaGetSymbolAddress((void**)&saout, g_saout);
    cudaGetSymbolAddress((void**)&tgt2,  g_tgt2);
    cudaGetSymbolAddress((void**)&q2,    g_q2);
    cudaGetSymbolAddress((void**)&offb,  g_off);
    cudaGetSymbolAddress((void**)&val,   g_value);
    cudaGetSymbolAddress((void**)&cain,  g_cain);
    cudaGetSymbolAddress((void**)&caout, g_caout);
    cudaGetSymbolAddress((void**)&tgt3,  g_tgt3);
    cudaGetSymbolAddress((void**)&f1,    g_f1);
    cudaGetSymbolAddress((void**)&f2,    g_f2);
    cudaGetSymbolAddress((void**)&wh,    g_wh);

    // 0) weight plane (fp16)
    {
        WDesc d;
        d.src[0]=in_proj_w; d.off[0]=W_INPROJ; d.n4[0]=196608/4;
        d.src[1]=out_sa_w;  d.off[1]=W_OUTSA;  d.n4[1]=65536/4;
        d.src[2]=value_w;   d.off[2]=W_VALUE;  d.n4[2]=65536/4;
        d.src[3]=off_w;     d.off[3]=W_OFF;    d.n4[3]=131072/4;
        d.src[4]=aw_w;      d.off[4]=W_AW;     d.n4[4]=65536/4;
        d.src[5]=out_ca_w;  d.off[5]=W_OUTCA;  d.n4[5]=65536/4;
        d.src[6]=lin1_w;    d.off[6]=W_LIN1;   d.n4[6]=262144/4;
        d.src[7]=lin2_w;    d.off[7]=W_LIN2;   d.n4[7]=262144/4;
        dim3 g((262144/4 + 255)/256, 8);
        cvt_w_kernel<<<g, 256>>>(d, wh);
    }

    // 1) q = tgt + query_mask
    add_kernel<<<TOKF/4/256, 256>>>(tgt, qmask, qbuf, TOKF/4);

    // 2) value projection over memory (batched over BS), pad-mask epilogue
    launch_mma(3, memory, BSZ*DIM, 256, wh+W_VALUE, DIM, value_b,
               nullptr, nullptr, 0,
               val, nullptr, DIM, (long)STOT*DIM,
               STOT, DIM, DIM, BSZ, pmask, STOT);

    // 3) Q+K merged (N=512), then V
    launch_mma(2, qbuf, DIM, 0, wh+W_INPROJ, DIM, in_proj_b,
               nullptr, nullptr, 0,
               qh, kh, 0, 0, NTOK, 512, DIM, 1, nullptr, 0);
    launch_mma(2, tgt, DIM, 0, wh+W_INPROJ+512*256, DIM, in_proj_b+512,
               nullptr, nullptr, 0,
               vh, nullptr, 0, 0, NTOK, 256, DIM, 1, nullptr, 0);

    // 4) fused self-attention
    {
        int smem = (300*36*2 + 150*32 + 8*320) * 4;
        cudaFuncSetAttribute(attn_kernel, cudaFuncAttributeMaxDynamicSharedMemorySize, smem);
        attn_kernel<<<128, 256, smem>>>(qh, kh, vh, sain);
    }

    // 5) self-attn out-proj + residual LN (norm2)
    launch_mma(0, sain, DIM, 0, wh+W_OUTSA, DIM, out_sa_b,
               nullptr, nullptr, 0,
               saout, nullptr, DIM, 0, NTOK, DIM, DIM, 1, nullptr, 0);
    ln_kernel<<<NTOK/8, 256>>>(tgt, saout, 0, norm2_g, norm2_b, tgt2);

    // 6) query2 = (tgt2 + mask) in (b,q,d) layout
    permadd_kernel<<<(TOKF/4 + 255)/256, 256>>>(tgt2, qmask, q2);

    // 7) offsets + aw logits merged (N=768, split at 512)
    launch_mma(0, q2, DIM, 0, wh+W_OFF, DIM, off_b,
               wh+W_AW, aw_b, 512,
               offb, nullptr, 768, 0, NTOK, 768, DIM, 1, nullptr, 0);

    // 8) deformable sampling
    deform_kernel<<<NTOK, 256>>>(offb, bbox, val, spatial, lstart, cain);

    // 9) cross-attn out-proj + residual LN (norm1)
    launch_mma(0, cain, DIM, 0, wh+W_OUTCA, DIM, out_ca_b,
               nullptr, nullptr, 0,
               caout, nullptr, DIM, 0, NTOK, DIM, DIM, 1, nullptr, 0);
    ln_kernel<<<NTOK/8, 256>>>(tgt2, caout, 1, norm1_g, norm1_b, tgt3);

    // 10) FFN + final LN (norm3) -> d_out
    launch_mma(1, tgt3, DIM, 0, wh+W_LIN1, DIM, lin1_b,
               nullptr, nullptr, 0,
               f1, nullptr, DFF, 0, NTOK, DFF, DIM, 1, nullptr, 0);
    launch_mma(0, f1, DFF, 0, wh+W_LIN2, DFF, lin2_b,
               nullptr, nullptr, 0,
               f2, nullptr, DIM, 0, NTOK, DIM, DFF, 1, nullptr, 0);
    ln_kernel<<<NTOK/8, 256>>>(tgt3, f2, 0, norm3_g, norm3_b, out);
}

// round 16
// speedup vs baseline: 1.6766x; 1.0544x over previous
#include <cuda_runtime.h>
#include <cuda_fp16.h>
#include <math.h>
#include <cstdint>

// ---------------- problem constants ----------------
#define NQ   300
#define BSZ  8
#define DIM  256
#define NH   8
#define DH   32
#define DFF  1024
#define STOT 13294
#define NTOK (NQ*BSZ)          // 2400
#define TOKF (NTOK*DIM)        // 614400

// weight plane offsets (elements)
#define W_INPROJ 0L
#define W_OUTSA  196608L
#define W_VALUE  262144L
#define W_OFF    327680L
#define W_AW     458752L
#define W_OUTCA  524288L
#define W_LIN1   589824L
#define W_LIN2   851968L
#define W_TOTAL  1114112L

// ---------------- scratch (static device globals; no allocations) ----------------
__device__ float g_qbuf [TOKF];
__device__ float g_qh   [TOKF];
__device__ float g_kh   [TOKF];
__device__ float g_vh   [TOKF];
__device__ float g_sain [TOKF];
__device__ float g_saout[TOKF];
__device__ float g_tgt2 [TOKF];
__device__ float g_q2   [TOKF];
__device__ float g_off  [NTOK*768];
__device__ __half g_value[(long)BSZ*STOT*DIM];   // fp16 value cache
__device__ float g_cain [TOKF];
__device__ float g_caout[TOKF];
__device__ float g_tgt3 [TOKF];
__device__ float g_f1   [NTOK*DFF];
__device__ float g_f2   [TOKF];
__device__ __half g_wh[W_TOTAL];   // weight fp16 plane

// ---------------- helpers ----------------
__device__ __forceinline__ uint32_t smem_u32(const void* p) {
    uint32_t a;
    asm("{ .reg .u64 t; cvta.to.shared.u64 t, %1; cvt.u32.u64 %0, t; }" : "=r"(a) : "l"(p));
    return a;
}
__device__ __forceinline__ unsigned pkh(__half a, __half b) {
    __half2 t = __halves2half2(a, b);
    return *reinterpret_cast<unsigned*>(&t);
}
__device__ __forceinline__ void mma_f16(float* d, const uint32_t* a, uint32_t b0, uint32_t b1) {
    asm volatile(
        "mma.sync.aligned.m16n8k16.row.col.f32.f16.f16.f32 "
        "{%0,%1,%2,%3}, {%4,%5,%6,%7}, {%8,%9}, {%0,%1,%2,%3};"
        : "+f"(d[0]), "+f"(d[1]), "+f"(d[2]), "+f"(d[3])
        : "r"(a[0]), "r"(a[1]), "r"(a[2]), "r"(a[3]), "r"(b0), "r"(b1));
}
__device__ __forceinline__ void ldmx4(uint32_t* r, uint32_t addr) {
    asm volatile("ldmatrix.sync.aligned.m8n8.x4.shared.b16 {%0,%1,%2,%3}, [%4];"
                 : "=r"(r[0]), "=r"(r[1]), "=r"(r[2]), "=r"(r[3]) : "r"(addr));
}
__device__ __forceinline__ uint2 cvt_a(float4 v) {
    return make_uint2(pkh(__float2half_rn(v.x), __float2half_rn(v.y)),
                      pkh(__float2half_rn(v.z), __float2half_rn(v.w)));
}
#define CP16(dst, src) \
    asm volatile("cp.async.cg.shared.global [%0], [%1], 16;" \
                 :: "r"(dst), "l"(src) : "memory")
#define CP_COMMIT() asm volatile("cp.async.commit_group;" ::: "memory")
#define CP_WAIT1()  asm volatile("cp.async.wait_group 1;" ::: "memory")

// ============ fp16 1-term GEMM, K-chunk 64: C = A(fp32->fp16) * W(fp16)^T + bias ============
// CTA 64x128, 256 thr, 8 warps of 32x32.
// A: register convert, 2-stage ping-pong (8KB/stage @0, @8192).
// B: cp.async 3-stage (16KB/stage @16384 + st*16384). Total smem 65536.
// EPI: 0 plain, 1 relu, 2 head-permute (C2 for n>=256), 3 pad-mask zero -> fp16 out (batched).
template<int EPI>
__global__ void __launch_bounds__(256, 2) mma_gemm(
    const float* __restrict__ A, int lda, long aOff,
    const __half* __restrict__ B, int ldw,
    const float* __restrict__ bias,
    const __half* W2, const float* bias2, int Nsplit,
    float* __restrict__ C, float* __restrict__ C2, int ldc, long cOff,
    int M, int K,
    const unsigned char* __restrict__ mask, long mOff)
{
    extern __shared__ __align__(128) unsigned char sm[];
    const uint32_t sb = smem_u32(sm);
    const int tid = threadIdx.x;
    const int bm = blockIdx.y * 64;
    const int bn = blockIdx.x * 128;
    A += (long)blockIdx.z * aOff;
    __half* Ch = nullptr;
    if (EPI == 3) Ch = (__half*)C + (long)blockIdx.z * cOff;
    else          C += (long)blockIdx.z * cOff;
    if (Nsplit && bn >= Nsplit) {
        B = W2 - (long)Nsplit * ldw;
        bias = bias2 - Nsplit;
    }

    const int warp = tid >> 5, lane = tid & 31;
    const int wm = warp & 1, wn = warp >> 1;

    // A: 64 rows x 64 k fp32 = 1024 float4 (4/thr)
    bool agd[4]; const float* aptr[4]; uint32_t asw[4];
#pragma unroll
    for (int j = 0; j < 4; j++) {
        int i = tid + j * 256;
        int row = i >> 4, kq = i & 15;
        int sub = kq >> 3, kq2 = kq & 7;
        agd[j] = (bm + row) < M;
        aptr[j] = A + (long)(bm + row) * lda + kq * 4;
        asw[j] = (uint32_t)(sub * 4096 + row * 64 + (((kq2 >> 1) ^ ((row >> 1) & 3)) << 4) + (kq2 & 1) * 8);
    }
    // B: 128 rows x 64 halves = 1024 x 16B (4/thr), cp.async
    const __half* bp[4]; uint32_t bsw[4];
#pragma unroll
    for (int j = 0; j < 4; j++) {
        int i = tid + j * 256;
        int row = i >> 3, c8 = i & 7;
        int sub = c8 >> 2, c = c8 & 3;
        bp[j] = B + (long)(bn + row) * ldw + sub * 32 + c * 8;
        bsw[j] = (uint32_t)(sub * 8192 + row * 64 + ((c ^ ((row >> 1) & 3)) << 4));
    }

    float acc[2][4][4];
#pragma unroll
    for (int mt = 0; mt < 2; mt++)
#pragma unroll
        for (int nt = 0; nt < 4; nt++)
#pragma unroll
            for (int r = 0; r < 4; r++) acc[mt][nt][r] = 0.f;

    const int nk = K >> 6;   // chunks of 64

#define ISSUE_B(kc, st) do { \
    if ((kc) < nk) { \
        const int kb = (kc) * 64; \
        const uint32_t so = sb + 16384u + (uint32_t)((st) * 16384); \
        CP16(so + bsw[0], bp[0] + kb); \
        CP16(so + bsw[1], bp[1] + kb); \
        CP16(so + bsw[2], bp[2] + kb); \
        CP16(so + bsw[3], bp[3] + kb); \
    } \
    CP_COMMIT(); \
} while (0)

    float4 av[4];

    // prologue
    ISSUE_B(0, 0);
    ISSUE_B(1, 1);
#pragma unroll
    for (int j = 0; j < 4; j++)
        av[j] = agd[j] ? *(const float4*)(aptr[j]) : make_float4(0.f,0.f,0.f,0.f);
#pragma unroll
    for (int j = 0; j < 4; j++)
        *(uint2*)(sm + asw[j]) = cvt_a(av[j]);
    if (nk > 1) {
#pragma unroll
        for (int j = 0; j < 4; j++)
            av[j] = agd[j] ? *(const float4*)(aptr[j] + 64) : make_float4(0.f,0.f,0.f,0.f);
    }
    CP_WAIT1();
    __syncthreads();

    for (int kc = 0; kc < nk; kc++) {
        ISSUE_B(kc + 2, (kc + 2) % 3);

        const uint32_t soa = sb + (uint32_t)((kc & 1) * 8192);
        const uint32_t sob = sb + 16384u + (uint32_t)((kc % 3) * 16384);

#pragma unroll
        for (int ks = 0; ks < 4; ks++) {
            const uint32_t suba = soa + (uint32_t)((ks >> 1) * 4096);
            const uint32_t subb = sob + (uint32_t)((ks >> 1) * 8192);
            const int kk = ks & 1;
            uint32_t af[2][4];
#pragma unroll
            for (int mt = 0; mt < 2; mt++) {
                int row = wm * 32 + mt * 16 + (lane & 7) + ((lane >> 3) & 1) * 8;
                int c = 2 * kk + (lane >> 4);
                uint32_t off = (uint32_t)(row * 64 + ((c ^ ((row >> 1) & 3)) << 4));
                ldmx4(af[mt], suba + off);
            }
            uint32_t bf[4][2];
#pragma unroll
            for (int np = 0; np < 2; np++) {
                int row = wn * 32 + np * 16 + (lane & 7) + (lane >> 4) * 8;
                int c = 2 * kk + ((lane >> 3) & 1);
                uint32_t off = (uint32_t)(row * 64 + ((c ^ ((row >> 1) & 3)) << 4));
                uint32_t t[4];
                ldmx4(t, subb + off);
                bf[2*np][0] = t[0]; bf[2*np][1] = t[1];
                bf[2*np+1][0] = t[2]; bf[2*np+1][1] = t[3];
            }
#pragma unroll
            for (int mt = 0; mt < 2; mt++)
#pragma unroll
                for (int nt = 0; nt < 4; nt++)
                    mma_f16(acc[mt][nt], af[mt], bf[nt][0], bf[nt][1]);
        }

        if (kc + 1 < nk) {
            const uint32_t po = (uint32_t)(((kc + 1) & 1) * 8192);
#pragma unroll
            for (int j = 0; j < 4; j++)
                *(uint2*)(sm + po + asw[j]) = cvt_a(av[j]);
            if (kc + 2 < nk) {
                int kb = (kc + 2) * 64;
#pragma unroll
                for (int j = 0; j < 4; j++)
                    av[j] = agd[j] ? *(const float4*)(aptr[j] + kb) : make_float4(0.f,0.f,0.f,0.f);
            }
        }
        CP_WAIT1();
        __syncthreads();
    }
#undef ISSUE_B

    // ---------------- epilogue ----------------
#pragma unroll
    for (int mt = 0; mt < 2; mt++) {
        int r0 = bm + wm * 32 + mt * 16 + (lane >> 2);
#pragma unroll
        for (int nt = 0; nt < 4; nt++) {
            int n0 = bn + wn * 32 + nt * 8 + (lane & 3) * 2;
            float b0 = bias[n0], b1 = bias[n0 + 1];
#pragma unroll
            for (int half = 0; half < 2; half++) {
                int r = r0 + half * 8;
                if (r >= M) continue;
                float v0 = acc[mt][nt][half * 2 + 0] + b0;
                float v1 = acc[mt][nt][half * 2 + 1] + b1;
                if (EPI == 1) { v0 = fmaxf(v0, 0.f); v1 = fmaxf(v1, 0.f); }
                if (EPI == 3) {
                    if (mask[(long)blockIdx.z * mOff + r]) { v0 = 0.f; v1 = 0.f; }
                    *(__half2*)(Ch + (long)r * ldc + n0) =
                        __halves2half2(__float2half_rn(v0), __float2half_rn(v1));
                } else if (EPI == 2) {
                    float* base = C; int nn = n0;
                    if (C2 && nn >= 256) { base = C2; nn -= 256; }
                    int q = r >> 3, bb = r & 7, hh = nn >> 5, d = nn & 31;
                    float* p = base + (((long)(bb * NH + hh)) * NQ + q) * DH + d;
                    p[0] = v0; p[1] = v1;
                } else {
                    float* p = C + (long)r * ldc + n0;
                    p[0] = v0; p[1] = v1;
                }
            }
        }
    }
}

static inline void launch_mma(int epi,
    const float* A, int lda, long aOff,
    const __half* B, int ldw, const float* bias,
    const __half* W2, const float* bias2, int Nsplit,
    float* C, float* C2, int ldc, long cOff,
    int M, int N, int K, int nz,
    const unsigned char* mask, long mOff)
{
    dim3 grid(N / 128, (M + 63) / 64, nz);
    const int SMEM = 65536;
#define LM(E) do { \
    cudaFuncSetAttribute(mma_gemm<E>, cudaFuncAttributeMaxDynamicSharedMemorySize, SMEM); \
    mma_gemm<E><<<grid,256,SMEM>>>(A,lda,aOff,B,ldw,bias,W2,bias2,Nsplit, \
                                   C,C2,ldc,cOff,M,K,mask,mOff); } while (0)
    switch (epi) {
        case 0: LM(0); break;
        case 1: LM(1); break;
        case 2: LM(2); break;
        case 3: LM(3); break;
    }
#undef LM
}

// ---------------- weight convert: fp32 -> fp16 plane ----------------
struct WDesc { const float* src[8]; long off[8]; int n4[8]; };
__global__ void cvt_w_kernel(WDesc d, __half* __restrict__ hi)
{
    int w = blockIdx.y;
    int i = blockIdx.x * blockDim.x + threadIdx.x;
    if (i >= d.n4[w]) return;
    float4 v = ((const float4*)d.src[w])[i];
    ((uint2*)(hi + d.off[w]))[i] = make_uint2(
        pkh(__float2half_rn(v.x), __float2half_rn(v.y)),
        pkh(__float2half_rn(v.z), __float2half_rn(v.w)));
}

// ---------------- elementwise ----------------
__global__ void add_kernel(const float* __restrict__ a, const float* __restrict__ b,
                           float* __restrict__ o, int n4)
{
    int i = blockIdx.x * blockDim.x + threadIdx.x;
    if (i < n4) {
        float4 x = ((const float4*)a)[i], y = ((const float4*)b)[i];
        ((float4*)o)[i] = make_float4(x.x+y.x, x.y+y.y, x.z+y.z, x.w+y.w);
    }
}

__global__ void permadd_kernel(const float* __restrict__ t2, const float* __restrict__ msk,
                               float* __restrict__ q2)
{
    int i = blockIdx.x * 256 + threadIdx.x;   // over TOKF/4 float4s
    if (i >= TOKF/4) return;
    int d4 = i & 63;
    int t = i >> 6;
    int q = t >> 3, b = t & 7;
    float4 x = ((const float4*)t2)[i], y = ((const float4*)msk)[i];
    ((float4*)q2)[((long)(b*NQ + q) << 6) + d4] = make_float4(x.x+y.x, x.y+y.y, x.z+y.z, x.w+y.w);
}

// ---------------- residual + layernorm ----------------
__global__ void __launch_bounds__(256) ln_kernel(
    const float* __restrict__ A, const float* __restrict__ B, int bBQ,
    const float* __restrict__ g, const float* __restrict__ be,
    float* __restrict__ out)
{
    int t = blockIdx.x * 8 + (threadIdx.x >> 5);
    int lane = threadIdx.x & 31;
    if (t >= NTOK) return;
    const float* ap = A + (long)t * DIM + lane*8;
    long bo;
    if (bBQ) { int q = t >> 3, b = t & 7; bo = (long)(b*NQ + q) * DIM; }
    else     { bo = (long)t * DIM; }
    const float* bp = B + bo + lane*8;

    float4 x0 = *(const float4*)ap,      x1 = *(const float4*)(ap + 4);
    float4 y0 = *(const float4*)bp,      y1 = *(const float4*)(bp + 4);
    float v[8] = {x0.x+y0.x, x0.y+y0.y, x0.z+y0.z, x0.w+y0.w,
                  x1.x+y1.x, x1.y+y1.y, x1.z+y1.z, x1.w+y1.w};
    float s = 0.f;
#pragma unroll
    for (int i = 0; i < 8; i++) s += v[i];
#pragma unroll
    for (int o = 16; o; o >>= 1) s += __shfl_xor_sync(0xffffffffu, s, o);
    float mu = s * (1.f/256.f);
    float s2 = 0.f;
#pragma unroll
    for (int i = 0; i < 8; i++) { float d = v[i] - mu; s2 += d*d; }
#pragma unroll
    for (int o = 16; o; o >>= 1) s2 += __shfl_xor_sync(0xffffffffu, s2, o);
    float inv = rsqrtf(s2 * (1.f/256.f) + 1e-5f);
    int c0 = lane*8;
    float* op = out + (long)t * DIM + c0;
#pragma unroll
    for (int i = 0; i < 8; i++)
        op[i] = (v[i] - mu) * inv * g[c0+i] + be[c0+i];
}

// ---------------- fused self-attention ----------------
__global__ void __launch_bounds__(256) attn_kernel(
    const float* __restrict__ qh, const float* __restrict__ kh,
    const float* __restrict__ vh, float* __restrict__ sa_in)
{
    extern __shared__ float smf[];
    const int bh   = blockIdx.x >> 1;
    const int half = blockIdx.x & 1;
    const int b = bh >> 3, h = bh & 7;
    float* Ks = smf;
    float* Vs = Ks + 300*36;
    float* Qs = Vs + 300*36;
    float* Ps = Qs + 150*32;

    const float scale = 0.17677669529663687f;
    const float* Kg = kh + (long)bh * NQ * DH;
    const float* Vg = vh + (long)bh * NQ * DH;
    const float* Qg = qh + (long)bh * NQ * DH + (long)half * 150 * DH;
    const int tid = threadIdx.x;

    for (int i = tid; i < 2400; i += 256) {
        int r = i >> 3, c4 = (i & 7) << 2;
        float4 kv = *(const float4*)(Kg + r*32 + c4);
        float4 vv = *(const float4*)(Vg + r*32 + c4);
        *(float4*)(Ks + r*36 + c4) = kv;
        *(float4*)(Vs + r*36 + c4) = vv;
    }
    for (int i = tid; i < 1200; i += 256) {
        int r = i >> 3, c4 = (i & 7) << 2;
        float4 qv = *(const float4*)(Qg + r*32 + c4);
        qv.x *= scale; qv.y *= scale; qv.z *= scale; qv.w *= scale;
        *(float4*)(Qs + r*32 + c4) = qv;
    }
    __syncthreads();

    const int warp = tid >> 5, lane = tid & 31;
    float* Pw = Ps + warp * 320;

    for (int q = warp; q < 150; q += 8) {
        float4 qr[8];
#pragma unroll
        for (int d4 = 0; d4 < 8; d4++) qr[d4] = *(const float4*)(Qs + q*32 + d4*4);

        float sc[10];
#pragma unroll
        for (int j = 0; j < 10; j++) {
            int k = j*32 + lane;
            float s = -1e30f;
            if (k < 300) {
                s = 0.f;
#pragma unroll
                for (int d4 = 0; d4 < 8; d4++) {
                    float4 kv = *(const float4*)(Ks + k*36 + d4*4);
                    s = fmaf(qr[d4].x, kv.x, s);
                    s = fmaf(qr[d4].y, kv.y, s);
                    s = fmaf(qr[d4].z, kv.z, s);
                    s = fmaf(qr[d4].w, kv.w, s);
                }
            }
            sc[j] = s;
        }
        float m = sc[0];
#pragma unroll
        for (int j = 1; j < 10; j++) m = fmaxf(m, sc[j]);
#pragma unroll
        for (int o = 16; o; o >>= 1) m = fmaxf(m, __shfl_xor_sync(0xffffffffu, m, o));
        float sum = 0.f;
#pragma unroll
        for (int j = 0; j < 10; j++) { sc[j] = expf(sc[j] - m); sum += sc[j]; }
#pragma unroll
        for (int o = 16; o; o >>= 1) sum += __shfl_xor_sync(0xffffffffu, sum, o);
        float inv = 1.f / sum;
#pragma unroll
        for (int j = 0; j < 10; j++) Pw[j*32 + lane] = sc[j] * inv;
        __syncwarp();

        float acc = 0.f;
#pragma unroll 4
        for (int k = 0; k < 300; k++)
            acc = fmaf(Pw[k], Vs[k*36 + lane], acc);

        int qg = half*150 + q;
        sa_in[((long)(qg*BSZ + b)) * DIM + h*DH + lane] = acc;
        __syncwarp();
    }
}

// ---------------- multi-scale deformable sampling (fp16 value) ----------------
__global__ void __launch_bounds__(256) deform_kernel(
    const float* __restrict__ offaw,
    const float* __restrict__ bbox, const __half* __restrict__ value,
    const int* __restrict__ spatial, const int* __restrict__ lstart,
    float* __restrict__ ca_in)
{
    __shared__ float s_w[8][32][4];
    __shared__ int   s_i[8][32][4];
    int bq = blockIdx.x;
    int b = bq / NQ, q = bq - b*NQ;
    int warp = threadIdx.x >> 5, lane = threadIdx.x & 31;

    const float* tok = offaw + (long)bq * 768;
    float a = tok[512 + warp*32 + lane];
    float m = a;
#pragma unroll
    for (int o = 16; o; o >>= 1) m = fmaxf(m, __shfl_xor_sync(0xffffffffu, m, o));
    float e = expf(a - m);
    float s = e;
#pragma unroll
    for (int o = 16; o; o >>= 1) s += __shfl_xor_sync(0xffffffffu, s, o);
    float p = e / s;

    float ox = tok[warp*64 + lane*2];
    float oy = tok[warp*64 + lane*2 + 1];
    const float* rb = bbox + ((long)q*BSZ + b)*4;
    float r0 = rb[0], r1 = rb[1], r2 = rb[2], r3 = rb[3];

    int lvl = lane >> 3;
    int H = spatial[lvl*2], W = spatial[lvl*2 + 1], ls = lstart[lvl];
    float Wf = (float)W, Hf = (float)H;
    float x = (r0 + ox*0.0625f*r2) * Wf - 0.5f;
    float y = (r1 + oy*0.0625f*r3) * Hf - 0.5f;
    float x0 = floorf(x), y0 = floorf(y);
    float fx = x - x0, fy = y - y0;

#pragma unroll
    for (int c = 0; c < 4; c++) {
        float xi = x0 + (float)(c & 1);
        float yi = y0 + (float)(c >> 1);
        float wgt = ((c & 1) ? fx : 1.f - fx) * ((c >> 1) ? fy : 1.f - fy);
        bool valid = (xi >= 0.f) && (xi < Wf) && (yi >= 0.f) && (yi < Hf);
        int xc = (int)fminf(fmaxf(xi, 0.f), Wf - 1.f);
        int yc = (int)fminf(fmaxf(yi, 0.f), Hf - 1.f);
        s_i[warp][lane][c] = ls + yc*W + xc;
        s_w[warp][lane][c] = valid ? wgt * p : 0.f;
    }
    __syncwarp();

    const __half* vb = value + (long)b * STOT * DIM + warp*DH + lane;
    float acc = 0.f;
    for (int lp = 0; lp < 32; lp++) {
#pragma unroll
        for (int c = 0; c < 4; c++) {
            float wgt = s_w[warp][lp][c];
            if (wgt != 0.f)
                acc = fmaf(wgt, __half2float(vb[(long)s_i[warp][lp][c] << 8]), acc);
        }
    }
    ca_in[(long)bq*DIM + warp*DH + lane] = acc;
}

// ---------------- host orchestration (single stream; no allocations) ----------------
extern "C" void kernel_launch(void* const* d_in, const int* in_sizes, int n_in,
                              void* d_out, int out_size)
{
    const float* tgt        = (const float*)d_in[0];
    const float* qmask      = (const float*)d_in[1];
    const float* bbox       = (const float*)d_in[2];
    const float* memory     = (const float*)d_in[4];
    const float* in_proj_w  = (const float*)d_in[5];
    const float* in_proj_b  = (const float*)d_in[6];
    const float* out_sa_w   = (const float*)d_in[7];
    const float* out_sa_b   = (const float*)d_in[8];
    const float* norm2_g    = (const float*)d_in[9];
    const float* norm2_b    = (const float*)d_in[10];
    const float* value_w    = (const float*)d_in[11];
    const float* value_b    = (const float*)d_in[12];
    const float* off_w      = (const float*)d_in[13];
    const float* off_b      = (const float*)d_in[14];
    const float* aw_w       = (const float*)d_in[15];
    const float* aw_b       = (const float*)d_in[16];
    const float* out_ca_w   = (const float*)d_in[17];
    const float* out_ca_b   = (const float*)d_in[18];
    const float* norm1_g    = (const float*)d_in[19];
    const float* norm1_b    = (const float*)d_in[20];
    const float* lin1_w     = (const float*)d_in[21];
    const float* lin1_b     = (const float*)d_in[22];
    const float* lin2_w     = (const float*)d_in[23];
    const float* lin2_b     = (const float*)d_in[24];
    const float* norm3_g    = (const float*)d_in[25];
    const float* norm3_b    = (const float*)d_in[26];
    const unsigned char* pmask = (const unsigned char*)d_in[27];
    const int* spatial      = (const int*)d_in[28];
    const int* lstart       = (const int*)d_in[29];
    float* out = (float*)d_out;

    float *qbuf,*qh,*kh,*vh,*sain,*saout,*tgt2,*q2,*offb,*cain,*caout,*tgt3,*f1,*f2;
    __half *wh,*val;
    cudaGetSymbolAddress((void**)&qbuf,  g_qbuf);
    cudaGetSymbolAddress((void**)&qh,    g_qh);
    cudaGetSymbolAddress((void**)&kh,    g_kh);
    cudaGetSymbolAddress((void**)&vh,    g_vh);
    cudaGetSymbolAddress((void**)&sain,  g_sain);
    cudaGetSymbolAddress((void**)&saout, g_saout);
    cudaGetSymbolAddress((void**)&tgt2,  g_tgt2);
    cudaGetSymbolAddress((void**)&q2,    g_q2);
    cudaGetSymbolAddress((void**)&offb,  g_off);
    cudaGetSymbolAddress((void**)&val,   g_value);
    cudaGetSymbolAddress((void**)&cain,  g_cain);
    cudaGetSymbolAddress((void**)&caout, g_caout);
    cudaGetSymbolAddress((void**)&tgt3,  g_tgt3);
    cudaGetSymbolAddress((void**)&f1,    g_f1);
    cudaGetSymbolAddress((void**)&f2,    g_f2);
    cudaGetSymbolAddress((void**)&wh,    g_wh);

    // 0) weight plane (fp16)
    {
        WDesc d;
        d.src[0]=in_proj_w; d.off[0]=W_INPROJ; d.n4[0]=196608/4;
        d.src[1]=out_sa_w;  d.off[1]=W_OUTSA;  d.n4[1]=65536/4;
        d.src[2]=value_w;   d.off[2]=W_VALUE;  d.n4[2]=65536/4;
        d.src[3]=off_w;     d.off[3]=W_OFF;    d.n4[3]=131072/4;
        d.src[4]=aw_w;      d.off[4]=W_AW;     d.n4[4]=65536/4;
        d.src[5]=out_ca_w;  d.off[5]=W_OUTCA;  d.n4[5]=65536/4;
        d.src[6]=lin1_w;    d.off[6]=W_LIN1;   d.n4[6]=262144/4;
        d.src[7]=lin2_w;    d.off[7]=W_LIN2;   d.n4[7]=262144/4;
        dim3 g((262144/4 + 255)/256, 8);
        cvt_w_kernel<<<g, 256>>>(d, wh);
    }

    // 1) q = tgt + query_mask
    add_kernel<<<TOKF/4/256, 256>>>(tgt, qmask, qbuf, TOKF/4);

    // 2) value projection over memory (batched over BS), pad-mask fp16 epilogue
    launch_mma(3, memory, BSZ*DIM, 256, wh+W_VALUE, DIM, value_b,
               nullptr, nullptr, 0,
               (float*)val, nullptr, DIM, (long)STOT*DIM,
               STOT, DIM, DIM, BSZ, pmask, STOT);

    // 3) Q+K merged (N=512), then V
    launch_mma(2, qbuf, DIM, 0, wh+W_INPROJ, DIM, in_proj_b,
               nullptr, nullptr, 0,
               qh, kh, 0, 0, NTOK, 512, DIM, 1, nullptr, 0);
    launch_mma(2, tgt, DIM, 0, wh+W_INPROJ+512*256, DIM, in_proj_b+512,
               nullptr, nullptr, 0,
               vh, nullptr, 0, 0, NTOK, 256, DIM, 1, nullptr, 0);

    // 4) fused self-attention
    {
        int smem = (300*36*2 + 150*32 + 8*320) * 4;
        cudaFuncSetAttribute(attn_kernel, cudaFuncAttributeMaxDynamicSharedMemorySize, smem);
        attn_kernel<<<128, 256, smem>>>(qh, kh, vh, sain);
    }

    // 5) self-attn out-proj + residual LN (norm2)
    launch_mma(0, sain, DIM, 0, wh+W_OUTSA, DIM, out_sa_b,
               nullptr, nullptr, 0,
               saout, nullptr, DIM, 0, NTOK, DIM, DIM, 1, nullptr, 0);
    ln_kernel<<<NTOK/8, 256>>>(tgt, saout, 0, norm2_g, norm2_b, tgt2);

    // 6) query2 = (tgt2 + mask) in (b,q,d) layout
    permadd_kernel<<<(TOKF/4 + 255)/256, 256>>>(tgt2, qmask, q2);

    // 7) offsets + aw logits merged (N=768, split at 512)
    launch_mma(0, q2, DIM, 0, wh+W_OFF, DIM, off_b,
               wh+W_AW, aw_b, 512,
               offb, nullptr, 768, 0, NTOK, 768, DIM, 1, nullptr, 0);

    // 8) deformable sampling (fp16 value)
    deform_kernel<<<NTOK, 256>>>(offb, bbox, val, spatial, lstart, cain);

    // 9) cross-attn out-proj + residual LN (norm1)
    launch_mma(0, cain, DIM, 0, wh+W_OUTCA, DIM, out_ca_b,
               nullptr, nullptr, 0,
               caout, nullptr, DIM, 0, NTOK, DIM, DIM, 1, nullptr, 0);
    ln_kernel<<<NTOK/8, 256>>>(tgt2, caout, 1, norm1_g, norm1_b, tgt3);

    // 10) FFN + final LN (norm3) -> d_out
    launch_mma(1, tgt3, DIM, 0, wh+W_LIN1, DIM, lin1_b,
               nullptr, nullptr, 0,
               f1, nullptr, DFF, 0, NTOK, DFF, DIM, 1, nullptr, 0);
    launch_mma(0, f1, DFF, 0, wh+W_LIN2, DFF, lin2_b,
               nullptr, nullptr, 0,
               f2, nullptr, DIM, 0, NTOK, DIM, DFF, 1, nullptr, 0);
    ln_kernel<<<NTOK/8, 256>>>(tgt3, f2, 0, norm3_g, norm3_b, out);
}